// round 7
// baseline (speedup 1.0000x reference)
#include <cuda_runtime.h>
#include <math.h>
#include <stdint.h>

// Problem constants
#define Bb   16
#define NPp  512
#define Nn   1024
#define Cc   1024
#define Hh   16
#define HDd  64
#define C3   3072
#define HIDh 4096
#define Mtok 8192   // B*NP

// ---------------- scratch (device globals) ----------------
__device__ float g_h   [(size_t)Mtok * Cc];
__device__ float g_qkv [(size_t)Mtok * C3];
__device__ float g_kf  [(size_t)Bb * Hh * Nn * HDd];
__device__ float g_vf  [(size_t)Bb * Hh * Nn * HDd];
__device__ float g_o   [(size_t)Mtok * Cc];
__device__ float g_x1  [(size_t)Mtok * Cc];
__device__ float g_hid [(size_t)Mtok * HIDh];
__device__ int   g_p2t [Bb * Nn];
// tf32-rounded weights
__device__ float g_wq  [(size_t)Cc * C3];
__device__ float g_wp  [(size_t)Cc * Cc];
__device__ float g_w1  [(size_t)Cc * HIDh];
__device__ float g_w2  [(size_t)HIDh * Cc];

// ---------------- helpers ----------------
__device__ __forceinline__ uint32_t f2tf32(float f) {
    uint32_t u;
    asm("cvt.rna.tf32.f32 %0, %1;" : "=r"(u) : "f"(f));
    return u;
}
__device__ __forceinline__ float rnd32(float f) { return __uint_as_float(f2tf32(f)); }

__device__ __forceinline__ void mma_tf32(float c[4], const uint32_t a[4], const uint32_t b[2]) {
    asm volatile(
        "mma.sync.aligned.m16n8k8.row.col.f32.tf32.tf32.f32 "
        "{%0,%1,%2,%3}, {%4,%5,%6,%7}, {%8,%9}, {%0,%1,%2,%3};"
        : "+f"(c[0]), "+f"(c[1]), "+f"(c[2]), "+f"(c[3])
        : "r"(a[0]), "r"(a[1]), "r"(a[2]), "r"(a[3]), "r"(b[0]), "r"(b[1]));
}
__device__ __forceinline__ void cp16(uint32_t saddr, const void* g) {
    asm volatile("cp.async.cg.shared.global [%0], [%1], 16;" :: "r"(saddr), "l"(g));
}
#define CP_COMMIT() asm volatile("cp.async.commit_group;")
#define CP_WAIT(n)  asm volatile("cp.async.wait_group %0;" :: "n"(n))

// ---------------- weight pre-round: all four weights in one launch ----------------
__global__ void round_all_kernel(const float4* __restrict__ wq_in, const float4* __restrict__ wp_in,
                                 const float4* __restrict__ w1_in, const float4* __restrict__ w2_in)
{
    const size_t NQ = (size_t)Cc * C3 / 4;     // 786432
    const size_t NP_ = (size_t)Cc * Cc / 4;    // 262144
    const size_t N1 = (size_t)Cc * HIDh / 4;   // 1048576
    const size_t N2 = (size_t)HIDh * Cc / 4;   // 1048576
    size_t i = (size_t)blockIdx.x * blockDim.x + threadIdx.x;
    const float4* src; float4* dst; size_t off;
    if (i < NQ)                    { src = wq_in; dst = (float4*)g_wq; off = i; }
    else if (i < NQ + NP_)         { src = wp_in; dst = (float4*)g_wp; off = i - NQ; }
    else if (i < NQ + NP_ + N1)    { src = w1_in; dst = (float4*)g_w1; off = i - NQ - NP_; }
    else if (i < NQ + NP_ + N1+N2) { src = w2_in; dst = (float4*)g_w2; off = i - NQ - NP_ - N1; }
    else return;
    float4 v = src[off];
    v.x = rnd32(v.x); v.y = rnd32(v.y); v.z = rnd32(v.z); v.w = rnd32(v.w);
    dst[off] = v;
}

// ---------------- tf32 mma.sync GEMM, cp.async 3-stage ----------------
// C[M,N] = act(A @ B + bias) + resid ;  A:[M,K] row-major, B:[K,N] row-major.
// Inputs pre-rounded to tf32. BM=256, BN=128, BK=16; 256 thr = 8 warps, warp tile 64x64.
template<bool HAS_BIAS, bool GELU_ACT, bool HAS_RES, bool ROUND_OUT>
__global__ void __launch_bounds__(256) mma_gemm(
    const float* __restrict__ A, const float* __restrict__ Bm, float* __restrict__ Cm,
    int K, int lda, int ldb, int ldc,
    const float* __restrict__ bias, const float* __restrict__ resid)
{
    const int AW = 20, BW = 136;                   // smem row strides (words)
    const int AWORDS = 256 * AW, BWORDS = 16 * BW; // 5120 + 2176
    const int STW = AWORDS + BWORDS;               // 7296 words per stage

    extern __shared__ float sm[];

    int t = threadIdx.x, lane = t & 31, warp = t >> 5;
    int g = lane >> 2, tg = lane & 3;
    int wm = (warp >> 1) * 64, wn = (warp & 1) * 64;
    int m0 = blockIdx.y * 256, n0 = blockIdx.x * 128;

    const float* Ab = A + (size_t)m0 * lda;
    const float* Bb_ = Bm + n0;

    float acc[4][8][4];
    #pragma unroll
    for (int i = 0; i < 4; i++)
        #pragma unroll
        for (int j = 0; j < 8; j++)
            #pragma unroll
            for (int l = 0; l < 4; l++) acc[i][j][l] = 0.f;

    auto issue = [&](int kt, int st) {
        float* As = sm + st * STW;
        float* Bs = As + AWORDS;
        const float* Ag = Ab + kt * 16;
        const float* Bg = Bb_ + (size_t)(kt * 16) * ldb;
        #pragma unroll
        for (int it = 0; it < 4; it++) {            // 1024 float4 for A (256x16)
            int c = t + it * 256;
            int r = c >> 2, c4 = (c & 3) * 4;
            cp16((uint32_t)__cvta_generic_to_shared(As + r * AW + c4),
                 Ag + (size_t)r * lda + c4);
        }
        #pragma unroll
        for (int it = 0; it < 2; it++) {            // 512 float4 for B (16x128)
            int c = t + it * 256;
            int k = c >> 5, n4 = (c & 31) * 4;
            cp16((uint32_t)__cvta_generic_to_shared(Bs + k * BW + n4),
                 Bg + (size_t)k * ldb + n4);
        }
        CP_COMMIT();
    };

    auto compute = [&](int st) {
        const uint32_t* As = reinterpret_cast<const uint32_t*>(sm + st * STW);
        const uint32_t* Bs = As + AWORDS;
        #pragma unroll
        for (int ks = 0; ks < 2; ks++) {
            int k0 = ks * 8;
            uint32_t af[4][4], bf[8][2];
            #pragma unroll
            for (int mt = 0; mt < 4; mt++) {
                int r = wm + mt * 16 + g;
                af[mt][0] = As[r * AW + k0 + tg];
                af[mt][1] = As[(r + 8) * AW + k0 + tg];
                af[mt][2] = As[r * AW + k0 + tg + 4];
                af[mt][3] = As[(r + 8) * AW + k0 + tg + 4];
            }
            #pragma unroll
            for (int nt = 0; nt < 8; nt++) {
                int c = wn + nt * 8 + g;
                bf[nt][0] = Bs[(k0 + tg) * BW + c];
                bf[nt][1] = Bs[(k0 + tg + 4) * BW + c];
            }
            #pragma unroll
            for (int mt = 0; mt < 4; mt++)
                #pragma unroll
                for (int nt = 0; nt < 8; nt++)
                    mma_tf32(acc[mt][nt], af[mt], bf[nt]);
        }
    };

    const int KT = K / 16;
    issue(0, 0);
    issue(1, 1);

    for (int kt = 0; kt < KT; kt++) {
        if (kt + 1 < KT) { CP_WAIT(1); } else { CP_WAIT(0); }
        __syncthreads();
        compute(kt % 3);
        if (kt + 2 < KT) issue(kt + 2, (kt + 2) % 3);
    }

    // ---- epilogue ----
    #pragma unroll
    for (int mt = 0; mt < 4; mt++) {
        int r0 = m0 + wm + mt * 16 + g;
        #pragma unroll
        for (int nt = 0; nt < 8; nt++) {
            int c = n0 + wn + nt * 8 + 2 * tg;
            #pragma unroll
            for (int half = 0; half < 2; half++) {
                int r = r0 + half * 8;
                float v0 = acc[mt][nt][half * 2 + 0];
                float v1 = acc[mt][nt][half * 2 + 1];
                if (HAS_BIAS) { v0 += bias[c]; v1 += bias[c + 1]; }
                if (GELU_ACT) {
                    v0 = 0.5f * v0 * (1.0f + erff(v0 * 0.70710678118654752f));
                    v1 = 0.5f * v1 * (1.0f + erff(v1 * 0.70710678118654752f));
                }
                if (HAS_RES) {
                    float2 rv = *reinterpret_cast<const float2*>(
                        resid + (size_t)r * ldc + c);
                    v0 += rv.x; v1 += rv.y;
                }
                if (ROUND_OUT) { v0 = rnd32(v0); v1 = rnd32(v1); }
                float2 ov; ov.x = v0; ov.y = v1;
                *reinterpret_cast<float2*>(Cm + (size_t)r * ldc + c) = ov;
            }
        }
    }
}

// ---------------- fused flash attention (tf32 mma.sync) ----------------
__global__ void __launch_bounds__(256) flash_kernel(
    const float* __restrict__ qkv, const float* __restrict__ kf,
    const float* __restrict__ vf, float* __restrict__ o)
{
    extern __shared__ float fsm[];
    const int TW = 68;
    const int KWORDS = 64 * TW;

    int t = threadIdx.x, lane = t & 31, w = t >> 5;
    int g = lane >> 2, tg = lane & 3;
    int bh = blockIdx.y, b = bh >> 4, h = bh & 15;
    int q0 = blockIdx.x * 128;

    const float* Qg = qkv + ((size_t)(b * NPp + q0)) * C3 + h * HDd;
    #pragma unroll
    for (int it = 0; it < 8; it++) {
        int id = t + it * 256;
        int r = id >> 4, c4 = (id & 15) * 4;
        float4 v = *reinterpret_cast<const float4*>(Qg + (size_t)r * C3 + c4);
        float* d = fsm + r * TW + c4;
        d[0] = v.x; d[1] = v.y; d[2] = v.z; d[3] = v.w;
    }
    __syncthreads();

    uint32_t qf[8][4];
    {
        int r0 = w * 16 + g;
        #pragma unroll
        for (int kk = 0; kk < 8; kk++) {
            qf[kk][0] = f2tf32(fsm[r0 * TW + kk * 8 + tg] * 0.125f);
            qf[kk][1] = f2tf32(fsm[(r0 + 8) * TW + kk * 8 + tg] * 0.125f);
            qf[kk][2] = f2tf32(fsm[r0 * TW + kk * 8 + tg + 4] * 0.125f);
            qf[kk][3] = f2tf32(fsm[(r0 + 8) * TW + kk * 8 + tg + 4] * 0.125f);
        }
    }
    __syncthreads();

    const float* Kg = kf + (size_t)bh * Nn * HDd;
    const float* Vg = vf + (size_t)bh * Nn * HDd;

    auto issue_tile = [&](int j, int buf) {
        float* Ks = fsm + buf * (2 * KWORDS);
        float* Vs = Ks + KWORDS;
        const float* kg = Kg + (size_t)j * 64 * HDd;
        const float* vg = Vg + (size_t)j * 64 * HDd;
        #pragma unroll
        for (int it = 0; it < 4; it++) {
            int id = t + it * 256;
            int r = id >> 4, c4 = (id & 15) * 4;
            cp16((uint32_t)__cvta_generic_to_shared(Ks + r * TW + c4), kg + r * HDd + c4);
            cp16((uint32_t)__cvta_generic_to_shared(Vs + r * TW + c4), vg + r * HDd + c4);
        }
    };

    float m_r[2] = {-1e30f, -1e30f};
    float l_r[2] = {0.f, 0.f};
    float o_acc[8][4];
    #pragma unroll
    for (int i = 0; i < 8; i++)
        #pragma unroll
        for (int j = 0; j < 4; j++) o_acc[i][j] = 0.f;

    const unsigned FULL = 0xffffffffu;
    const int srcA = (lane & ~3) | (tg >> 1);
    const int srcB = srcA + 2;

    issue_tile(0, 0);
    CP_COMMIT();

    for (int j = 0; j < Nn / 64; j++) {
        int buf = j & 1;
        if (j + 1 < Nn / 64) { issue_tile(j + 1, buf ^ 1); CP_COMMIT(); CP_WAIT(1); }
        else                 { CP_WAIT(0); }
        __syncthreads();

        const uint32_t* Ku = reinterpret_cast<const uint32_t*>(fsm + buf * (2 * KWORDS));
        const uint32_t* Vu = Ku + KWORDS;

        float s[8][4];
        #pragma unroll
        for (int nt = 0; nt < 8; nt++)
            #pragma unroll
            for (int i = 0; i < 4; i++) s[nt][i] = 0.f;
        #pragma unroll
        for (int kk = 0; kk < 8; kk++) {
            #pragma unroll
            for (int nt = 0; nt < 8; nt++) {
                uint32_t bb[2];
                bb[0] = Ku[(nt * 8 + g) * TW + kk * 8 + tg];
                bb[1] = Ku[(nt * 8 + g) * TW + kk * 8 + tg + 4];
                mma_tf32(s[nt], qf[kk], bb);
            }
        }

        float mn0 = m_r[0], mn1 = m_r[1];
        #pragma unroll
        for (int nt = 0; nt < 8; nt++) {
            mn0 = fmaxf(mn0, fmaxf(s[nt][0], s[nt][1]));
            mn1 = fmaxf(mn1, fmaxf(s[nt][2], s[nt][3]));
        }
        mn0 = fmaxf(mn0, __shfl_xor_sync(FULL, mn0, 1));
        mn0 = fmaxf(mn0, __shfl_xor_sync(FULL, mn0, 2));
        mn1 = fmaxf(mn1, __shfl_xor_sync(FULL, mn1, 1));
        mn1 = fmaxf(mn1, __shfl_xor_sync(FULL, mn1, 2));
        float c0 = __expf(m_r[0] - mn0);
        float c1 = __expf(m_r[1] - mn1);
        m_r[0] = mn0; m_r[1] = mn1;

        float pf_[8][4];
        float rs0 = 0.f, rs1 = 0.f;
        #pragma unroll
        for (int nt = 0; nt < 8; nt++) {
            pf_[nt][0] = __expf(s[nt][0] - mn0);
            pf_[nt][1] = __expf(s[nt][1] - mn0);
            pf_[nt][2] = __expf(s[nt][2] - mn1);
            pf_[nt][3] = __expf(s[nt][3] - mn1);
            rs0 += pf_[nt][0] + pf_[nt][1];
            rs1 += pf_[nt][2] + pf_[nt][3];
        }
        rs0 += __shfl_xor_sync(FULL, rs0, 1); rs0 += __shfl_xor_sync(FULL, rs0, 2);
        rs1 += __shfl_xor_sync(FULL, rs1, 1); rs1 += __shfl_xor_sync(FULL, rs1, 2);
        l_r[0] = l_r[0] * c0 + rs0;
        l_r[1] = l_r[1] * c1 + rs1;
        #pragma unroll
        for (int nt = 0; nt < 8; nt++) {
            o_acc[nt][0] *= c0; o_acc[nt][1] *= c0;
            o_acc[nt][2] *= c1; o_acc[nt][3] *= c1;
        }

        #pragma unroll
        for (int kk2 = 0; kk2 < 8; kk2++) {
            float v0 = pf_[kk2][0], v1 = pf_[kk2][1], v2 = pf_[kk2][2], v3 = pf_[kk2][3];
            float w0 = __shfl_sync(FULL, v0, srcA), w1 = __shfl_sync(FULL, v1, srcA);
            float w2 = __shfl_sync(FULL, v2, srcA), w3 = __shfl_sync(FULL, v3, srcA);
            float y0 = __shfl_sync(FULL, v0, srcB), y1 = __shfl_sync(FULL, v1, srcB);
            float y2 = __shfl_sync(FULL, v2, srcB), y3 = __shfl_sync(FULL, v3, srcB);
            bool odd = (tg & 1);
            uint32_t af[4];
            af[0] = f2tf32(odd ? w1 : w0);
            af[1] = f2tf32(odd ? w3 : w2);
            af[2] = f2tf32(odd ? y1 : y0);
            af[3] = f2tf32(odd ? y3 : y2);
            #pragma unroll
            for (int nt2 = 0; nt2 < 8; nt2++) {
                uint32_t bb[2];
                bb[0] = Vu[(kk2 * 8 + tg) * TW + nt2 * 8 + g];
                bb[1] = Vu[(kk2 * 8 + tg + 4) * TW + nt2 * 8 + g];
                mma_tf32(o_acc[nt2], af, bb);
            }
        }
        __syncthreads();
    }

    float inv0 = 1.0f / l_r[0], inv1 = 1.0f / l_r[1];
    float* Og = o + ((size_t)(b * NPp + q0 + w * 16 + g)) * Cc + h * HDd;
    #pragma unroll
    for (int nt2 = 0; nt2 < 8; nt2++) {
        int c = nt2 * 8 + 2 * tg;
        float2 r0v; r0v.x = rnd32(o_acc[nt2][0] * inv0); r0v.y = rnd32(o_acc[nt2][1] * inv0);
        float2 r1v; r1v.x = rnd32(o_acc[nt2][2] * inv1); r1v.y = rnd32(o_acc[nt2][3] * inv1);
        *reinterpret_cast<float2*>(Og + c) = r0v;
        *reinterpret_cast<float2*>(Og + (size_t)8 * Cc + c) = r1v;
    }
}

// ---------------- LayerNorm (tf32-rounded output) ----------------
__global__ void ln_kernel(const float* __restrict__ x, const float* __restrict__ g,
                          const float* __restrict__ b, float* __restrict__ out)
{
    size_t row = blockIdx.x;
    const float* xr = x + row * Cc;
    float* orow = out + row * Cc;
    int t = threadIdx.x;
    float4 v = reinterpret_cast<const float4*>(xr)[t];
    float s  = v.x + v.y + v.z + v.w;
    float ss = v.x*v.x + v.y*v.y + v.z*v.z + v.w*v.w;
    #pragma unroll
    for (int o = 16; o > 0; o >>= 1) {
        s  += __shfl_xor_sync(0xffffffffu, s,  o);
        ss += __shfl_xor_sync(0xffffffffu, ss, o);
    }
    __shared__ float r0[8], r1[8];
    if ((t & 31) == 0) { r0[t >> 5] = s; r1[t >> 5] = ss; }
    __syncthreads();
    s = 0.f; ss = 0.f;
    #pragma unroll
    for (int i = 0; i < 8; i++) { s += r0[i]; ss += r1[i]; }
    float mu  = s * (1.0f / Cc);
    float var = ss * (1.0f / Cc) - mu * mu;
    float inv = rsqrtf(var + 1e-5f);
    float4 gv = reinterpret_cast<const float4*>(g)[t];
    float4 bv = reinterpret_cast<const float4*>(b)[t];
    float4 r;
    r.x = rnd32((v.x - mu) * inv * gv.x + bv.x);
    r.y = rnd32((v.y - mu) * inv * gv.y + bv.y);
    r.z = rnd32((v.z - mu) * inv * gv.z + bv.z);
    r.w = rnd32((v.w - mu) * inv * gv.w + bv.w);
    reinterpret_cast<float4*>(orow)[t] = r;
}

// ---------------- mask scan ----------------
__global__ void p2t_kernel(const unsigned* __restrict__ mask)
{
    int b = blockIdx.x;
    if (threadIdx.x == 0) {
        int cnt = 0;
        for (int n = 0; n < Nn; n++) {
            if (mask[b * Nn + n] != 0u) g_p2t[b * Nn + n] = cnt++;
            else                        g_p2t[b * Nn + n] = -1;
        }
    }
}

// ---------------- KV fill (float4), pre-rounds to tf32 ----------------
__global__ void kvfill_kernel(const float4* __restrict__ ck, const float4* __restrict__ cv)
{
    size_t idx = (size_t)blockIdx.x * blockDim.x + threadIdx.x;
    int d4 = idx & 15;
    int n  = (idx >> 4) & (Nn - 1);
    int h  = (idx >> 14) & (Hh - 1);
    int b  = (int)(idx >> 18);
    int tok = g_p2t[b * Nn + n];
    float4 kv, vv;
    if (tok >= 0) {
        const float4* qkv4 = reinterpret_cast<const float4*>(g_qkv);
        size_t q = ((size_t)(b * NPp + tok)) * (C3 / 4) + (Cc / 4) + h * (HDd / 4) + d4;
        kv = qkv4[q];
        vv = qkv4[q + Cc / 4];
    } else {
        kv = ck[idx];
        vv = cv[idx];
    }
    kv.x = rnd32(kv.x); kv.y = rnd32(kv.y); kv.z = rnd32(kv.z); kv.w = rnd32(kv.w);
    vv.x = rnd32(vv.x); vv.y = rnd32(vv.y); vv.z = rnd32(vv.z); vv.w = rnd32(vv.w);
    reinterpret_cast<float4*>(g_kf)[idx] = kv;
    reinterpret_cast<float4*>(g_vf)[idx] = vv;
}

// ---------------- launch ----------------
extern "C" void kernel_launch(void* const* d_in, const int* in_sizes, int n_in,
                              void* d_out, int out_size)
{
    const float*    x      = (const float*)   d_in[0];
    const float*    cachek = (const float*)   d_in[1];
    const float*    cachev = (const float*)   d_in[2];
    const unsigned* mask   = (const unsigned*)d_in[3];
    const float*    qkv_w  = (const float*)   d_in[4];
    const float*    qkv_b  = (const float*)   d_in[5];
    const float*    proj_w = (const float*)   d_in[6];
    const float*    proj_b = (const float*)   d_in[7];
    const float*    n1_g   = (const float*)   d_in[8];
    const float*    n1_b   = (const float*)   d_in[9];
    const float*    n2_g   = (const float*)   d_in[10];
    const float*    n2_b   = (const float*)   d_in[11];
    const float*    fc1_w  = (const float*)   d_in[12];
    const float*    fc1_b  = (const float*)   d_in[13];
    const float*    fc2_w  = (const float*)   d_in[14];
    const float*    fc2_b  = (const float*)   d_in[15];
    float* out = (float*)d_out;

    float *h, *qkv, *kf, *vf, *o, *x1, *hid, *wq, *wp, *w1, *w2;
    cudaGetSymbolAddress((void**)&h,   g_h);
    cudaGetSymbolAddress((void**)&qkv, g_qkv);
    cudaGetSymbolAddress((void**)&kf,  g_kf);
    cudaGetSymbolAddress((void**)&vf,  g_vf);
    cudaGetSymbolAddress((void**)&o,   g_o);
    cudaGetSymbolAddress((void**)&x1,  g_x1);
    cudaGetSymbolAddress((void**)&hid, g_hid);
    cudaGetSymbolAddress((void**)&wq,  g_wq);
    cudaGetSymbolAddress((void**)&wp,  g_wp);
    cudaGetSymbolAddress((void**)&w1,  g_w1);
    cudaGetSymbolAddress((void**)&w2,  g_w2);

    const int GEMM_SMEM  = 3 * (256 * 20 + 16 * 136) * 4;   // 87552 B
    const int FLASH_SMEM = 2 * 2 * 64 * 68 * 4;             // 69632 B
    cudaFuncSetAttribute((const void*)mma_gemm<true, false, false, true>,
                         cudaFuncAttributeMaxDynamicSharedMemorySize, GEMM_SMEM);
    cudaFuncSetAttribute((const void*)mma_gemm<true, false, true, false>,
                         cudaFuncAttributeMaxDynamicSharedMemorySize, GEMM_SMEM);
    cudaFuncSetAttribute((const void*)mma_gemm<true, true, false, true>,
                         cudaFuncAttributeMaxDynamicSharedMemorySize, GEMM_SMEM);
    cudaFuncSetAttribute(flash_kernel,
                         cudaFuncAttributeMaxDynamicSharedMemorySize, FLASH_SMEM);

    // 0. pre-round all weights to tf32 (one launch; 3145728 float4 total)
    round_all_kernel<<<3145728 / 256, 256>>>(
        (const float4*)qkv_w, (const float4*)proj_w,
        (const float4*)fc1_w, (const float4*)fc2_w);

    // 1. LN1 (rounded out)
    ln_kernel<<<Mtok, 256>>>(x, n1_g, n1_b, h);

    // 2. QKV = h @ wq + qkv_b  (rounded out)
    mma_gemm<true, false, false, true><<<dim3(C3 / 128, Mtok / 256), 256, GEMM_SMEM>>>(
        h, wq, qkv, Cc, Cc, C3, C3, qkv_b, nullptr);

    // 3. mask scan
    p2t_kernel<<<Bb, 32>>>(mask);

    // 4. KV full fill (tf32-rounded)
    kvfill_kernel<<<((Bb * Hh * Nn * HDd) / 4) / 256, 256>>>(
        (const float4*)cachek, (const float4*)cachev);

    // 5-7. fused attention (o rounded out)
    flash_kernel<<<dim3(NPp / 128, Bb * Hh), 256, FLASH_SMEM>>>(qkv, kf, vf, o);

    // 8. x1 = x + o @ wp + proj_b
    mma_gemm<true, false, true, false><<<dim3(Cc / 128, Mtok / 256), 256, GEMM_SMEM>>>(
        o, wp, x1, Cc, Cc, Cc, Cc, proj_b, x);

    // 9. LN2 (rounded out)
    ln_kernel<<<Mtok, 256>>>(x1, n2_g, n2_b, h);

    // 10. hid = gelu(h @ w1 + fc1_b)  (rounded out)
    mma_gemm<true, true, false, true><<<dim3(HIDh / 128, Mtok / 256), 256, GEMM_SMEM>>>(
        h, w1, hid, Cc, Cc, HIDh, HIDh, fc1_b, nullptr);

    // 11. out = x1 + hid @ w2 + fc2_b
    mma_gemm<true, false, true, false><<<dim3(Cc / 128, Mtok / 256), 256, GEMM_SMEM>>>(
        hid, w2, out, HIDh, HIDh, Cc, Cc, fc2_b, x1);
}

// round 8
// speedup vs baseline: 1.0383x; 1.0383x over previous
#include <cuda_runtime.h>
#include <math.h>
#include <stdint.h>

// Problem constants
#define Bb   16
#define NPp  512
#define Nn   1024
#define Cc   1024
#define Hh   16
#define HDd  64
#define C3   3072
#define HIDh 4096
#define Mtok 8192   // B*NP

// ---------------- scratch (device globals) ----------------
__device__ float g_h   [(size_t)Mtok * Cc];
__device__ float g_qkv [(size_t)Mtok * C3];
__device__ float g_kf  [(size_t)Bb * Hh * Nn * HDd];
__device__ float g_vf  [(size_t)Bb * Hh * Nn * HDd];
__device__ float g_o   [(size_t)Mtok * Cc];
__device__ float g_x1  [(size_t)Mtok * Cc];
__device__ float g_hid [(size_t)Mtok * HIDh];
__device__ int   g_p2t [Bb * Nn];
// tf32-rounded weights
__device__ float g_wq  [(size_t)Cc * C3];
__device__ float g_wp  [(size_t)Cc * Cc];
__device__ float g_w1  [(size_t)Cc * HIDh];
__device__ float g_w2  [(size_t)HIDh * Cc];

// ---------------- helpers ----------------
__device__ __forceinline__ uint32_t f2tf32(float f) {
    uint32_t u;
    asm("cvt.rna.tf32.f32 %0, %1;" : "=r"(u) : "f"(f));
    return u;
}
__device__ __forceinline__ float rnd32(float f) { return __uint_as_float(f2tf32(f)); }

__device__ __forceinline__ void mma_tf32(float c[4], const uint32_t a[4], const uint32_t b[2]) {
    asm volatile(
        "mma.sync.aligned.m16n8k8.row.col.f32.tf32.tf32.f32 "
        "{%0,%1,%2,%3}, {%4,%5,%6,%7}, {%8,%9}, {%0,%1,%2,%3};"
        : "+f"(c[0]), "+f"(c[1]), "+f"(c[2]), "+f"(c[3])
        : "r"(a[0]), "r"(a[1]), "r"(a[2]), "r"(a[3]), "r"(b[0]), "r"(b[1]));
}
__device__ __forceinline__ void cp16(uint32_t saddr, const void* g) {
    asm volatile("cp.async.cg.shared.global [%0], [%1], 16;" :: "r"(saddr), "l"(g));
}
#define CP_COMMIT() asm volatile("cp.async.commit_group;")
#define CP_WAIT(n)  asm volatile("cp.async.wait_group %0;" :: "n"(n))

// ---------------- weight pre-round: all four weights in one launch ----------------
__global__ void round_all_kernel(const float4* __restrict__ wq_in, const float4* __restrict__ wp_in,
                                 const float4* __restrict__ w1_in, const float4* __restrict__ w2_in)
{
    const size_t NQ = (size_t)Cc * C3 / 4;
    const size_t NP_ = (size_t)Cc * Cc / 4;
    const size_t N1 = (size_t)Cc * HIDh / 4;
    const size_t N2 = (size_t)HIDh * Cc / 4;
    size_t i = (size_t)blockIdx.x * blockDim.x + threadIdx.x;
    const float4* src; float4* dst; size_t off;
    if (i < NQ)                    { src = wq_in; dst = (float4*)g_wq; off = i; }
    else if (i < NQ + NP_)         { src = wp_in; dst = (float4*)g_wp; off = i - NQ; }
    else if (i < NQ + NP_ + N1)    { src = w1_in; dst = (float4*)g_w1; off = i - NQ - NP_; }
    else if (i < NQ + NP_ + N1+N2) { src = w2_in; dst = (float4*)g_w2; off = i - NQ - NP_ - N1; }
    else return;
    float4 v = src[off];
    v.x = rnd32(v.x); v.y = rnd32(v.y); v.z = rnd32(v.z); v.w = rnd32(v.w);
    dst[off] = v;
}

// ---------------- tf32 mma.sync GEMM, cp.async 4-stage (R6 geometry) ----------------
// C[M,N] = act(A @ B + bias) + resid ;  A:[M,K] row-major, B:[K,N] row-major.
// BM=128, BN=128, BK=16; 256 thr = 8 warps, warp tile 64x32.
template<bool HAS_BIAS, bool GELU_ACT, bool HAS_RES, bool ROUND_OUT>
__global__ void __launch_bounds__(256) mma_gemm(
    const float* __restrict__ A, const float* __restrict__ Bm, float* __restrict__ Cm,
    int K, int lda, int ldb, int ldc,
    const float* __restrict__ bias, const float* __restrict__ resid)
{
    const int AW = 20, BW = 136;
    const int AWORDS = 128 * AW, BWORDS = 16 * BW;
    const int STW = AWORDS + BWORDS;               // 4736 words per stage
    const int NSTAGE = 4;

    extern __shared__ float sm[];

    int t = threadIdx.x, lane = t & 31, warp = t >> 5;
    int g = lane >> 2, tg = lane & 3;
    int wm = (warp >> 2) * 64, wn = (warp & 3) * 32;
    int m0 = blockIdx.y * 128, n0 = blockIdx.x * 128;

    const float* Ab = A + (size_t)m0 * lda;
    const float* Bb_ = Bm + n0;

    float acc[4][4][4];
    #pragma unroll
    for (int i = 0; i < 4; i++)
        #pragma unroll
        for (int j = 0; j < 4; j++)
            #pragma unroll
            for (int l = 0; l < 4; l++) acc[i][j][l] = 0.f;

    auto issue = [&](int kt, int st) {
        float* As = sm + st * STW;
        float* Bs = As + AWORDS;
        const float* Ag = Ab + kt * 16;
        const float* Bg = Bb_ + (size_t)(kt * 16) * ldb;
        #pragma unroll
        for (int it = 0; it < 2; it++) {
            int c = t + it * 256;
            int r = c >> 2, c4 = (c & 3) * 4;
            cp16((uint32_t)__cvta_generic_to_shared(As + r * AW + c4),
                 Ag + (size_t)r * lda + c4);
        }
        #pragma unroll
        for (int it = 0; it < 2; it++) {
            int c = t + it * 256;
            int k = c >> 5, n4 = (c & 31) * 4;
            cp16((uint32_t)__cvta_generic_to_shared(Bs + k * BW + n4),
                 Bg + (size_t)k * ldb + n4);
        }
        CP_COMMIT();
    };

    auto compute = [&](int st) {
        const uint32_t* As = reinterpret_cast<const uint32_t*>(sm + st * STW);
        const uint32_t* Bs = As + AWORDS;
        #pragma unroll
        for (int ks = 0; ks < 2; ks++) {
            int k0 = ks * 8;
            uint32_t af[4][4], bf[4][2];
            #pragma unroll
            for (int mt = 0; mt < 4; mt++) {
                int r = wm + mt * 16 + g;
                af[mt][0] = As[r * AW + k0 + tg];
                af[mt][1] = As[(r + 8) * AW + k0 + tg];
                af[mt][2] = As[r * AW + k0 + tg + 4];
                af[mt][3] = As[(r + 8) * AW + k0 + tg + 4];
            }
            #pragma unroll
            for (int nt = 0; nt < 4; nt++) {
                int c = wn + nt * 8 + g;
                bf[nt][0] = Bs[(k0 + tg) * BW + c];
                bf[nt][1] = Bs[(k0 + tg + 4) * BW + c];
            }
            #pragma unroll
            for (int mt = 0; mt < 4; mt++)
                #pragma unroll
                for (int nt = 0; nt < 4; nt++)
                    mma_tf32(acc[mt][nt], af[mt], bf[nt]);
        }
    };

    const int KT = K / 16;
    issue(0, 0);
    issue(1, 1);
    issue(2, 2);

    for (int kt = 0; kt < KT; kt++) {
        if (kt + 2 < KT)      { CP_WAIT(2); }
        else if (kt + 1 < KT) { CP_WAIT(1); }
        else                  { CP_WAIT(0); }
        __syncthreads();
        if (kt + 3 < KT) issue(kt + 3, (kt + 3) % NSTAGE);
        compute(kt % NSTAGE);
        __syncthreads();
    }

    // ---- epilogue ----
    #pragma unroll
    for (int mt = 0; mt < 4; mt++) {
        int r0 = m0 + wm + mt * 16 + g;
        #pragma unroll
        for (int nt = 0; nt < 4; nt++) {
            int c = n0 + wn + nt * 8 + 2 * tg;
            #pragma unroll
            for (int half = 0; half < 2; half++) {
                int r = r0 + half * 8;
                float v0 = acc[mt][nt][half * 2 + 0];
                float v1 = acc[mt][nt][half * 2 + 1];
                if (HAS_BIAS) { v0 += bias[c]; v1 += bias[c + 1]; }
                if (GELU_ACT) {
                    v0 = 0.5f * v0 * (1.0f + erff(v0 * 0.70710678118654752f));
                    v1 = 0.5f * v1 * (1.0f + erff(v1 * 0.70710678118654752f));
                }
                if (HAS_RES) {
                    float2 rv = *reinterpret_cast<const float2*>(
                        resid + (size_t)r * ldc + c);
                    v0 += rv.x; v1 += rv.y;
                }
                if (ROUND_OUT) { v0 = rnd32(v0); v1 = rnd32(v1); }
                float2 ov; ov.x = v0; ov.y = v1;
                *reinterpret_cast<float2*>(Cm + (size_t)r * ldc + c) = ov;
            }
        }
    }
}

// ---------------- fused flash attention (tf32 mma.sync) ----------------
__global__ void __launch_bounds__(256) flash_kernel(
    const float* __restrict__ qkv, const float* __restrict__ kf,
    const float* __restrict__ vf, float* __restrict__ o)
{
    extern __shared__ float fsm[];
    const int TW = 68;
    const int KWORDS = 64 * TW;

    int t = threadIdx.x, lane = t & 31, w = t >> 5;
    int g = lane >> 2, tg = lane & 3;
    int bh = blockIdx.y, b = bh >> 4, h = bh & 15;
    int q0 = blockIdx.x * 128;

    const float* Qg = qkv + ((size_t)(b * NPp + q0)) * C3 + h * HDd;
    #pragma unroll
    for (int it = 0; it < 8; it++) {
        int id = t + it * 256;
        int r = id >> 4, c4 = (id & 15) * 4;
        float4 v = *reinterpret_cast<const float4*>(Qg + (size_t)r * C3 + c4);
        float* d = fsm + r * TW + c4;
        d[0] = v.x; d[1] = v.y; d[2] = v.z; d[3] = v.w;
    }
    __syncthreads();

    uint32_t qf[8][4];
    {
        int r0 = w * 16 + g;
        #pragma unroll
        for (int kk = 0; kk < 8; kk++) {
            qf[kk][0] = f2tf32(fsm[r0 * TW + kk * 8 + tg] * 0.125f);
            qf[kk][1] = f2tf32(fsm[(r0 + 8) * TW + kk * 8 + tg] * 0.125f);
            qf[kk][2] = f2tf32(fsm[r0 * TW + kk * 8 + tg + 4] * 0.125f);
            qf[kk][3] = f2tf32(fsm[(r0 + 8) * TW + kk * 8 + tg + 4] * 0.125f);
        }
    }
    __syncthreads();

    const float* Kg = kf + (size_t)bh * Nn * HDd;
    const float* Vg = vf + (size_t)bh * Nn * HDd;

    auto issue_tile = [&](int j, int buf) {
        float* Ks = fsm + buf * (2 * KWORDS);
        float* Vs = Ks + KWORDS;
        const float* kg = Kg + (size_t)j * 64 * HDd;
        const float* vg = Vg + (size_t)j * 64 * HDd;
        #pragma unroll
        for (int it = 0; it < 4; it++) {
            int id = t + it * 256;
            int r = id >> 4, c4 = (id & 15) * 4;
            cp16((uint32_t)__cvta_generic_to_shared(Ks + r * TW + c4), kg + r * HDd + c4);
            cp16((uint32_t)__cvta_generic_to_shared(Vs + r * TW + c4), vg + r * HDd + c4);
        }
    };

    float m_r[2] = {-1e30f, -1e30f};
    float l_r[2] = {0.f, 0.f};
    float o_acc[8][4];
    #pragma unroll
    for (int i = 0; i < 8; i++)
        #pragma unroll
        for (int j = 0; j < 4; j++) o_acc[i][j] = 0.f;

    const unsigned FULL = 0xffffffffu;
    const int srcA = (lane & ~3) | (tg >> 1);
    const int srcB = srcA + 2;

    issue_tile(0, 0);
    CP_COMMIT();

    for (int j = 0; j < Nn / 64; j++) {
        int buf = j & 1;
        if (j + 1 < Nn / 64) { issue_tile(j + 1, buf ^ 1); CP_COMMIT(); CP_WAIT(1); }
        else                 { CP_WAIT(0); }
        __syncthreads();

        const uint32_t* Ku = reinterpret_cast<const uint32_t*>(fsm + buf * (2 * KWORDS));
        const uint32_t* Vu = Ku + KWORDS;

        float s[8][4];
        #pragma unroll
        for (int nt = 0; nt < 8; nt++)
            #pragma unroll
            for (int i = 0; i < 4; i++) s[nt][i] = 0.f;
        #pragma unroll
        for (int kk = 0; kk < 8; kk++) {
            #pragma unroll
            for (int nt = 0; nt < 8; nt++) {
                uint32_t bb[2];
                bb[0] = Ku[(nt * 8 + g) * TW + kk * 8 + tg];
                bb[1] = Ku[(nt * 8 + g) * TW + kk * 8 + tg + 4];
                mma_tf32(s[nt], qf[kk], bb);
            }
        }

        float mn0 = m_r[0], mn1 = m_r[1];
        #pragma unroll
        for (int nt = 0; nt < 8; nt++) {
            mn0 = fmaxf(mn0, fmaxf(s[nt][0], s[nt][1]));
            mn1 = fmaxf(mn1, fmaxf(s[nt][2], s[nt][3]));
        }
        mn0 = fmaxf(mn0, __shfl_xor_sync(FULL, mn0, 1));
        mn0 = fmaxf(mn0, __shfl_xor_sync(FULL, mn0, 2));
        mn1 = fmaxf(mn1, __shfl_xor_sync(FULL, mn1, 1));
        mn1 = fmaxf(mn1, __shfl_xor_sync(FULL, mn1, 2));
        float c0 = __expf(m_r[0] - mn0);
        float c1 = __expf(m_r[1] - mn1);
        m_r[0] = mn0; m_r[1] = mn1;

        float pf_[8][4];
        float rs0 = 0.f, rs1 = 0.f;
        #pragma unroll
        for (int nt = 0; nt < 8; nt++) {
            pf_[nt][0] = __expf(s[nt][0] - mn0);
            pf_[nt][1] = __expf(s[nt][1] - mn0);
            pf_[nt][2] = __expf(s[nt][2] - mn1);
            pf_[nt][3] = __expf(s[nt][3] - mn1);
            rs0 += pf_[nt][0] + pf_[nt][1];
            rs1 += pf_[nt][2] + pf_[nt][3];
        }
        rs0 += __shfl_xor_sync(FULL, rs0, 1); rs0 += __shfl_xor_sync(FULL, rs0, 2);
        rs1 += __shfl_xor_sync(FULL, rs1, 1); rs1 += __shfl_xor_sync(FULL, rs1, 2);
        l_r[0] = l_r[0] * c0 + rs0;
        l_r[1] = l_r[1] * c1 + rs1;
        #pragma unroll
        for (int nt = 0; nt < 8; nt++) {
            o_acc[nt][0] *= c0; o_acc[nt][1] *= c0;
            o_acc[nt][2] *= c1; o_acc[nt][3] *= c1;
        }

        #pragma unroll
        for (int kk2 = 0; kk2 < 8; kk2++) {
            float v0 = pf_[kk2][0], v1 = pf_[kk2][1], v2 = pf_[kk2][2], v3 = pf_[kk2][3];
            float w0 = __shfl_sync(FULL, v0, srcA), w1 = __shfl_sync(FULL, v1, srcA);
            float w2 = __shfl_sync(FULL, v2, srcA), w3 = __shfl_sync(FULL, v3, srcA);
            float y0 = __shfl_sync(FULL, v0, srcB), y1 = __shfl_sync(FULL, v1, srcB);
            float y2 = __shfl_sync(FULL, v2, srcB), y3 = __shfl_sync(FULL, v3, srcB);
            bool odd = (tg & 1);
            uint32_t af[4];
            af[0] = f2tf32(odd ? w1 : w0);
            af[1] = f2tf32(odd ? w3 : w2);
            af[2] = f2tf32(odd ? y1 : y0);
            af[3] = f2tf32(odd ? y3 : y2);
            #pragma unroll
            for (int nt2 = 0; nt2 < 8; nt2++) {
                uint32_t bb[2];
                bb[0] = Vu[(kk2 * 8 + tg) * TW + nt2 * 8 + g];
                bb[1] = Vu[(kk2 * 8 + tg + 4) * TW + nt2 * 8 + g];
                mma_tf32(o_acc[nt2], af, bb);
            }
        }
        __syncthreads();
    }

    float inv0 = 1.0f / l_r[0], inv1 = 1.0f / l_r[1];
    float* Og = o + ((size_t)(b * NPp + q0 + w * 16 + g)) * Cc + h * HDd;
    #pragma unroll
    for (int nt2 = 0; nt2 < 8; nt2++) {
        int c = nt2 * 8 + 2 * tg;
        float2 r0v; r0v.x = rnd32(o_acc[nt2][0] * inv0); r0v.y = rnd32(o_acc[nt2][1] * inv0);
        float2 r1v; r1v.x = rnd32(o_acc[nt2][2] * inv1); r1v.y = rnd32(o_acc[nt2][3] * inv1);
        *reinterpret_cast<float2*>(Og + c) = r0v;
        *reinterpret_cast<float2*>(Og + (size_t)8 * Cc + c) = r1v;
    }
}

// ---------------- LayerNorm (tf32-rounded output) ----------------
__global__ void ln_kernel(const float* __restrict__ x, const float* __restrict__ g,
                          const float* __restrict__ b, float* __restrict__ out)
{
    size_t row = blockIdx.x;
    const float* xr = x + row * Cc;
    float* orow = out + row * Cc;
    int t = threadIdx.x;
    float4 v = reinterpret_cast<const float4*>(xr)[t];
    float s  = v.x + v.y + v.z + v.w;
    float ss = v.x*v.x + v.y*v.y + v.z*v.z + v.w*v.w;
    #pragma unroll
    for (int o = 16; o > 0; o >>= 1) {
        s  += __shfl_xor_sync(0xffffffffu, s,  o);
        ss += __shfl_xor_sync(0xffffffffu, ss, o);
    }
    __shared__ float r0[8], r1[8];
    if ((t & 31) == 0) { r0[t >> 5] = s; r1[t >> 5] = ss; }
    __syncthreads();
    s = 0.f; ss = 0.f;
    #pragma unroll
    for (int i = 0; i < 8; i++) { s += r0[i]; ss += r1[i]; }
    float mu  = s * (1.0f / Cc);
    float var = ss * (1.0f / Cc) - mu * mu;
    float inv = rsqrtf(var + 1e-5f);
    float4 gv = reinterpret_cast<const float4*>(g)[t];
    float4 bv = reinterpret_cast<const float4*>(b)[t];
    float4 r;
    r.x = rnd32((v.x - mu) * inv * gv.x + bv.x);
    r.y = rnd32((v.y - mu) * inv * gv.y + bv.y);
    r.z = rnd32((v.z - mu) * inv * gv.z + bv.z);
    r.w = rnd32((v.w - mu) * inv * gv.w + bv.w);
    reinterpret_cast<float4*>(orow)[t] = r;
}

// ---------------- mask scan: warp-parallel prefix scan ----------------
__global__ void p2t_kernel(const unsigned* __restrict__ mask)
{
    int b = blockIdx.x;
    int lane = threadIdx.x;               // 32 lanes, each handles 32 positions
    const unsigned* mrow = mask + b * Nn;
    int base = lane * 32;
    unsigned bits = 0;
    int cnt = 0;
    #pragma unroll
    for (int i = 0; i < 32; i++) {
        unsigned mv = mrow[base + i] != 0u;
        bits |= mv << i;
        cnt += (int)mv;
    }
    // exclusive scan of cnt across lanes
    int excl = cnt;
    #pragma unroll
    for (int o = 1; o < 32; o <<= 1) {
        int v = __shfl_up_sync(0xffffffffu, excl, o);
        if (lane >= o) excl += v;
    }
    excl -= cnt;
    int run = excl;
    #pragma unroll
    for (int i = 0; i < 32; i++) {
        bool mv = (bits >> i) & 1u;
        g_p2t[b * Nn + base + i] = mv ? run : -1;
        run += mv ? 1 : 0;
    }
}

// ---------------- KV fill (float4), pre-rounds to tf32 ----------------
__global__ void kvfill_kernel(const float4* __restrict__ ck, const float4* __restrict__ cv)
{
    size_t idx = (size_t)blockIdx.x * blockDim.x + threadIdx.x;
    int d4 = idx & 15;
    int n  = (idx >> 4) & (Nn - 1);
    int h  = (idx >> 14) & (Hh - 1);
    int b  = (int)(idx >> 18);
    int tok = g_p2t[b * Nn + n];
    float4 kv, vv;
    if (tok >= 0) {
        const float4* qkv4 = reinterpret_cast<const float4*>(g_qkv);
        size_t q = ((size_t)(b * NPp + tok)) * (C3 / 4) + (Cc / 4) + h * (HDd / 4) + d4;
        kv = qkv4[q];
        vv = qkv4[q + Cc / 4];
    } else {
        kv = ck[idx];
        vv = cv[idx];
    }
    kv.x = rnd32(kv.x); kv.y = rnd32(kv.y); kv.z = rnd32(kv.z); kv.w = rnd32(kv.w);
    vv.x = rnd32(vv.x); vv.y = rnd32(vv.y); vv.z = rnd32(vv.z); vv.w = rnd32(vv.w);
    reinterpret_cast<float4*>(g_kf)[idx] = kv;
    reinterpret_cast<float4*>(g_vf)[idx] = vv;
}

// ---------------- launch ----------------
extern "C" void kernel_launch(void* const* d_in, const int* in_sizes, int n_in,
                              void* d_out, int out_size)
{
    const float*    x      = (const float*)   d_in[0];
    const float*    cachek = (const float*)   d_in[1];
    const float*    cachev = (const float*)   d_in[2];
    const unsigned* mask   = (const unsigned*)d_in[3];
    const float*    qkv_w  = (const float*)   d_in[4];
    const float*    qkv_b  = (const float*)   d_in[5];
    const float*    proj_w = (const float*)   d_in[6];
    const float*    proj_b = (const float*)   d_in[7];
    const float*    n1_g   = (const float*)   d_in[8];
    const float*    n1_b   = (const float*)   d_in[9];
    const float*    n2_g   = (const float*)   d_in[10];
    const float*    n2_b   = (const float*)   d_in[11];
    const float*    fc1_w  = (const float*)   d_in[12];
    const float*    fc1_b  = (const float*)   d_in[13];
    const float*    fc2_w  = (const float*)   d_in[14];
    const float*    fc2_b  = (const float*)   d_in[15];
    float* out = (float*)d_out;

    float *h, *qkv, *kf, *vf, *o, *x1, *hid, *wq, *wp, *w1, *w2;
    cudaGetSymbolAddress((void**)&h,   g_h);
    cudaGetSymbolAddress((void**)&qkv, g_qkv);
    cudaGetSymbolAddress((void**)&kf,  g_kf);
    cudaGetSymbolAddress((void**)&vf,  g_vf);
    cudaGetSymbolAddress((void**)&o,   g_o);
    cudaGetSymbolAddress((void**)&x1,  g_x1);
    cudaGetSymbolAddress((void**)&hid, g_hid);
    cudaGetSymbolAddress((void**)&wq,  g_wq);
    cudaGetSymbolAddress((void**)&wp,  g_wp);
    cudaGetSymbolAddress((void**)&w1,  g_w1);
    cudaGetSymbolAddress((void**)&w2,  g_w2);

    const int GEMM_SMEM  = 4 * (128 * 20 + 16 * 136) * 4;   // 75776 B (4 stages)
    const int FLASH_SMEM = 2 * 2 * 64 * 68 * 4;             // 69632 B
    cudaFuncSetAttribute((const void*)mma_gemm<true, false, false, true>,
                         cudaFuncAttributeMaxDynamicSharedMemorySize, GEMM_SMEM);
    cudaFuncSetAttribute((const void*)mma_gemm<true, false, true, false>,
                         cudaFuncAttributeMaxDynamicSharedMemorySize, GEMM_SMEM);
    cudaFuncSetAttribute((const void*)mma_gemm<true, true, false, true>,
                         cudaFuncAttributeMaxDynamicSharedMemorySize, GEMM_SMEM);
    cudaFuncSetAttribute(flash_kernel,
                         cudaFuncAttributeMaxDynamicSharedMemorySize, FLASH_SMEM);

    // 0. pre-round all weights to tf32 (one launch)
    round_all_kernel<<<3145728 / 256, 256>>>(
        (const float4*)qkv_w, (const float4*)proj_w,
        (const float4*)fc1_w, (const float4*)fc2_w);

    // 1. LN1 (rounded out)
    ln_kernel<<<Mtok, 256>>>(x, n1_g, n1_b, h);

    // 2. QKV = h @ wq + qkv_b  (rounded out)
    mma_gemm<true, false, false, true><<<dim3(C3 / 128, Mtok / 128), 256, GEMM_SMEM>>>(
        h, wq, qkv, Cc, Cc, C3, C3, qkv_b, nullptr);

    // 3. mask scan (warp-parallel)
    p2t_kernel<<<Bb, 32>>>(mask);

    // 4. KV full fill (tf32-rounded)
    kvfill_kernel<<<((Bb * Hh * Nn * HDd) / 4) / 256, 256>>>(
        (const float4*)cachek, (const float4*)cachev);

    // 5-7. fused attention (o rounded out)
    flash_kernel<<<dim3(NPp / 128, Bb * Hh), 256, FLASH_SMEM>>>(qkv, kf, vf, o);

    // 8. x1 = x + o @ wp + proj_b
    mma_gemm<true, false, true, false><<<dim3(Cc / 128, Mtok / 128), 256, GEMM_SMEM>>>(
        o, wp, x1, Cc, Cc, Cc, Cc, proj_b, x);

    // 9. LN2 (rounded out)
    ln_kernel<<<Mtok, 256>>>(x1, n2_g, n2_b, h);

    // 10. hid = gelu(h @ w1 + fc1_b)  (rounded out)
    mma_gemm<true, true, false, true><<<dim3(HIDh / 128, Mtok / 128), 256, GEMM_SMEM>>>(
        h, w1, hid, Cc, Cc, HIDh, HIDh, fc1_b, nullptr);

    // 11. out = x1 + hid @ w2 + fc2_b
    mma_gemm<true, false, true, false><<<dim3(Cc / 128, Mtok / 128), 256, GEMM_SMEM>>>(
        hid, w2, out, HIDh, HIDh, Cc, Cc, fc2_b, x1);
}

// round 9
// speedup vs baseline: 1.0772x; 1.0374x over previous
#include <cuda_runtime.h>
#include <math.h>
#include <stdint.h>

// Problem constants
#define Bb   16
#define NPp  512
#define Nn   1024
#define Cc   1024
#define Hh   16
#define HDd  64
#define C3   3072
#define HIDh 4096
#define Mtok 8192   // B*NP

// ---------------- scratch (device globals) ----------------
__device__ float g_h   [(size_t)Mtok * Cc];
__device__ float g_qkv [(size_t)Mtok * C3];
__device__ float g_kf  [(size_t)Bb * Hh * Nn * HDd];
__device__ float g_vf  [(size_t)Bb * Hh * Nn * HDd];
__device__ float g_o   [(size_t)Mtok * Cc];
__device__ float g_x1  [(size_t)Mtok * Cc];
__device__ float g_hid [(size_t)Mtok * HIDh];
__device__ int   g_p2t [Bb * Nn];
// tf32-rounded weights
__device__ float g_wq  [(size_t)Cc * C3];
__device__ float g_wp  [(size_t)Cc * Cc];
__device__ float g_w1  [(size_t)Cc * HIDh];
__device__ float g_w2  [(size_t)HIDh * Cc];

// ---------------- helpers ----------------
__device__ __forceinline__ uint32_t f2tf32(float f) {
    uint32_t u;
    asm("cvt.rna.tf32.f32 %0, %1;" : "=r"(u) : "f"(f));
    return u;
}
__device__ __forceinline__ float rnd32(float f) { return __uint_as_float(f2tf32(f)); }

__device__ __forceinline__ void mma_tf32(float c[4], const uint32_t a[4], const uint32_t b[2]) {
    asm volatile(
        "mma.sync.aligned.m16n8k8.row.col.f32.tf32.tf32.f32 "
        "{%0,%1,%2,%3}, {%4,%5,%6,%7}, {%8,%9}, {%0,%1,%2,%3};"
        : "+f"(c[0]), "+f"(c[1]), "+f"(c[2]), "+f"(c[3])
        : "r"(a[0]), "r"(a[1]), "r"(a[2]), "r"(a[3]), "r"(b[0]), "r"(b[1]));
}
__device__ __forceinline__ void cp16(uint32_t saddr, const void* g) {
    asm volatile("cp.async.cg.shared.global [%0], [%1], 16;" :: "r"(saddr), "l"(g));
}
#define CP_COMMIT() asm volatile("cp.async.commit_group;")
#define CP_WAIT(n)  asm volatile("cp.async.wait_group %0;" :: "n"(n))

// ---------------- weight pre-round: all four weights in one launch ----------------
__global__ void round_all_kernel(const float4* __restrict__ wq_in, const float4* __restrict__ wp_in,
                                 const float4* __restrict__ w1_in, const float4* __restrict__ w2_in)
{
    const size_t NQ = (size_t)Cc * C3 / 4;
    const size_t NP_ = (size_t)Cc * Cc / 4;
    const size_t N1 = (size_t)Cc * HIDh / 4;
    const size_t N2 = (size_t)HIDh * Cc / 4;
    size_t i = (size_t)blockIdx.x * blockDim.x + threadIdx.x;
    const float4* src; float4* dst; size_t off;
    if (i < NQ)                    { src = wq_in; dst = (float4*)g_wq; off = i; }
    else if (i < NQ + NP_)         { src = wp_in; dst = (float4*)g_wp; off = i - NQ; }
    else if (i < NQ + NP_ + N1)    { src = w1_in; dst = (float4*)g_w1; off = i - NQ - NP_; }
    else if (i < NQ + NP_ + N1+N2) { src = w2_in; dst = (float4*)g_w2; off = i - NQ - NP_ - N1; }
    else return;
    float4 v = src[off];
    v.x = rnd32(v.x); v.y = rnd32(v.y); v.z = rnd32(v.z); v.w = rnd32(v.w);
    dst[off] = v;
}

// ---------------- tf32 mma.sync GEMM, cp.async 3-stage (R6 exact) ----------------
// C[M,N] = act(A @ B + bias) + resid ;  A:[M,K] row-major, B:[K,N] row-major.
// BM=128, BN=128, BK=16; 256 thr = 8 warps, warp tile 64x32.
template<bool HAS_BIAS, bool GELU_ACT, bool HAS_RES, bool ROUND_OUT>
__global__ void __launch_bounds__(256) mma_gemm(
    const float* __restrict__ A, const float* __restrict__ Bm, float* __restrict__ Cm,
    int K, int lda, int ldb, int ldc,
    const float* __restrict__ bias, const float* __restrict__ resid)
{
    const int AW = 20, BW = 136;
    const int AWORDS = 128 * AW, BWORDS = 16 * BW;
    const int STW = AWORDS + BWORDS;               // 4736 words per stage

    extern __shared__ float sm[];

    int t = threadIdx.x, lane = t & 31, warp = t >> 5;
    int g = lane >> 2, tg = lane & 3;
    int wm = (warp >> 2) * 64, wn = (warp & 3) * 32;
    int m0 = blockIdx.y * 128, n0 = blockIdx.x * 128;

    const float* Ab = A + (size_t)m0 * lda;
    const float* Bb_ = Bm + n0;

    float acc[4][4][4];
    #pragma unroll
    for (int i = 0; i < 4; i++)
        #pragma unroll
        for (int j = 0; j < 4; j++)
            #pragma unroll
            for (int l = 0; l < 4; l++) acc[i][j][l] = 0.f;

    auto issue = [&](int kt, int st) {
        float* As = sm + st * STW;
        float* Bs = As + AWORDS;
        const float* Ag = Ab + kt * 16;
        const float* Bg = Bb_ + (size_t)(kt * 16) * ldb;
        #pragma unroll
        for (int it = 0; it < 2; it++) {
            int c = t + it * 256;
            int r = c >> 2, c4 = (c & 3) * 4;
            cp16((uint32_t)__cvta_generic_to_shared(As + r * AW + c4),
                 Ag + (size_t)r * lda + c4);
        }
        #pragma unroll
        for (int it = 0; it < 2; it++) {
            int c = t + it * 256;
            int k = c >> 5, n4 = (c & 31) * 4;
            cp16((uint32_t)__cvta_generic_to_shared(Bs + k * BW + n4),
                 Bg + (size_t)k * ldb + n4);
        }
        CP_COMMIT();
    };

    auto compute = [&](int st) {
        const uint32_t* As = reinterpret_cast<const uint32_t*>(sm + st * STW);
        const uint32_t* Bs = As + AWORDS;
        #pragma unroll
        for (int ks = 0; ks < 2; ks++) {
            int k0 = ks * 8;
            uint32_t af[4][4], bf[4][2];
            #pragma unroll
            for (int mt = 0; mt < 4; mt++) {
                int r = wm + mt * 16 + g;
                af[mt][0] = As[r * AW + k0 + tg];
                af[mt][1] = As[(r + 8) * AW + k0 + tg];
                af[mt][2] = As[r * AW + k0 + tg + 4];
                af[mt][3] = As[(r + 8) * AW + k0 + tg + 4];
            }
            #pragma unroll
            for (int nt = 0; nt < 4; nt++) {
                int c = wn + nt * 8 + g;
                bf[nt][0] = Bs[(k0 + tg) * BW + c];
                bf[nt][1] = Bs[(k0 + tg + 4) * BW + c];
            }
            #pragma unroll
            for (int mt = 0; mt < 4; mt++)
                #pragma unroll
                for (int nt = 0; nt < 4; nt++)
                    mma_tf32(acc[mt][nt], af[mt], bf[nt]);
        }
    };

    const int KT = K / 16;
    issue(0, 0);
    issue(1, 1);

    for (int kt = 0; kt < KT; kt++) {
        if (kt + 1 < KT) { CP_WAIT(1); } else { CP_WAIT(0); }
        __syncthreads();
        compute(kt % 3);
        if (kt + 2 < KT) issue(kt + 2, (kt + 2) % 3);
    }

    // ---- epilogue ----
    #pragma unroll
    for (int mt = 0; mt < 4; mt++) {
        int r0 = m0 + wm + mt * 16 + g;
        #pragma unroll
        for (int nt = 0; nt < 4; nt++) {
            int c = n0 + wn + nt * 8 + 2 * tg;
            #pragma unroll
            for (int half = 0; half < 2; half++) {
                int r = r0 + half * 8;
                float v0 = acc[mt][nt][half * 2 + 0];
                float v1 = acc[mt][nt][half * 2 + 1];
                if (HAS_BIAS) { v0 += bias[c]; v1 += bias[c + 1]; }
                if (GELU_ACT) {
                    v0 = 0.5f * v0 * (1.0f + erff(v0 * 0.70710678118654752f));
                    v1 = 0.5f * v1 * (1.0f + erff(v1 * 0.70710678118654752f));
                }
                if (HAS_RES) {
                    float2 rv = *reinterpret_cast<const float2*>(
                        resid + (size_t)r * ldc + c);
                    v0 += rv.x; v1 += rv.y;
                }
                if (ROUND_OUT) { v0 = rnd32(v0); v1 = rnd32(v1); }
                float2 ov; ov.x = v0; ov.y = v1;
                *reinterpret_cast<float2*>(Cm + (size_t)r * ldc + c) = ov;
            }
        }
    }
}

// ---------------- fused flash attention (tf32 mma.sync) ----------------
__global__ void __launch_bounds__(256) flash_kernel(
    const float* __restrict__ qkv, const float* __restrict__ kf,
    const float* __restrict__ vf, float* __restrict__ o)
{
    extern __shared__ float fsm[];
    const int TW = 68;
    const int KWORDS = 64 * TW;

    int t = threadIdx.x, lane = t & 31, w = t >> 5;
    int g = lane >> 2, tg = lane & 3;
    int bh = blockIdx.y, b = bh >> 4, h = bh & 15;
    int q0 = blockIdx.x * 128;

    const float* Qg = qkv + ((size_t)(b * NPp + q0)) * C3 + h * HDd;
    #pragma unroll
    for (int it = 0; it < 8; it++) {
        int id = t + it * 256;
        int r = id >> 4, c4 = (id & 15) * 4;
        float4 v = *reinterpret_cast<const float4*>(Qg + (size_t)r * C3 + c4);
        float* d = fsm + r * TW + c4;
        d[0] = v.x; d[1] = v.y; d[2] = v.z; d[3] = v.w;
    }
    __syncthreads();

    uint32_t qf[8][4];
    {
        int r0 = w * 16 + g;
        #pragma unroll
        for (int kk = 0; kk < 8; kk++) {
            qf[kk][0] = f2tf32(fsm[r0 * TW + kk * 8 + tg] * 0.125f);
            qf[kk][1] = f2tf32(fsm[(r0 + 8) * TW + kk * 8 + tg] * 0.125f);
            qf[kk][2] = f2tf32(fsm[r0 * TW + kk * 8 + tg + 4] * 0.125f);
            qf[kk][3] = f2tf32(fsm[(r0 + 8) * TW + kk * 8 + tg + 4] * 0.125f);
        }
    }
    __syncthreads();

    const float* Kg = kf + (size_t)bh * Nn * HDd;
    const float* Vg = vf + (size_t)bh * Nn * HDd;

    auto issue_tile = [&](int j, int buf) {
        float* Ks = fsm + buf * (2 * KWORDS);
        float* Vs = Ks + KWORDS;
        const float* kg = Kg + (size_t)j * 64 * HDd;
        const float* vg = Vg + (size_t)j * 64 * HDd;
        #pragma unroll
        for (int it = 0; it < 4; it++) {
            int id = t + it * 256;
            int r = id >> 4, c4 = (id & 15) * 4;
            cp16((uint32_t)__cvta_generic_to_shared(Ks + r * TW + c4), kg + r * HDd + c4);
            cp16((uint32_t)__cvta_generic_to_shared(Vs + r * TW + c4), vg + r * HDd + c4);
        }
    };

    float m_r[2] = {-1e30f, -1e30f};
    float l_r[2] = {0.f, 0.f};
    float o_acc[8][4];
    #pragma unroll
    for (int i = 0; i < 8; i++)
        #pragma unroll
        for (int j = 0; j < 4; j++) o_acc[i][j] = 0.f;

    const unsigned FULL = 0xffffffffu;
    const int srcA = (lane & ~3) | (tg >> 1);
    const int srcB = srcA + 2;

    issue_tile(0, 0);
    CP_COMMIT();

    for (int j = 0; j < Nn / 64; j++) {
        int buf = j & 1;
        if (j + 1 < Nn / 64) { issue_tile(j + 1, buf ^ 1); CP_COMMIT(); CP_WAIT(1); }
        else                 { CP_WAIT(0); }
        __syncthreads();

        const uint32_t* Ku = reinterpret_cast<const uint32_t*>(fsm + buf * (2 * KWORDS));
        const uint32_t* Vu = Ku + KWORDS;

        float s[8][4];
        #pragma unroll
        for (int nt = 0; nt < 8; nt++)
            #pragma unroll
            for (int i = 0; i < 4; i++) s[nt][i] = 0.f;
        #pragma unroll
        for (int kk = 0; kk < 8; kk++) {
            #pragma unroll
            for (int nt = 0; nt < 8; nt++) {
                uint32_t bb[2];
                bb[0] = Ku[(nt * 8 + g) * TW + kk * 8 + tg];
                bb[1] = Ku[(nt * 8 + g) * TW + kk * 8 + tg + 4];
                mma_tf32(s[nt], qf[kk], bb);
            }
        }

        float mn0 = m_r[0], mn1 = m_r[1];
        #pragma unroll
        for (int nt = 0; nt < 8; nt++) {
            mn0 = fmaxf(mn0, fmaxf(s[nt][0], s[nt][1]));
            mn1 = fmaxf(mn1, fmaxf(s[nt][2], s[nt][3]));
        }
        mn0 = fmaxf(mn0, __shfl_xor_sync(FULL, mn0, 1));
        mn0 = fmaxf(mn0, __shfl_xor_sync(FULL, mn0, 2));
        mn1 = fmaxf(mn1, __shfl_xor_sync(FULL, mn1, 1));
        mn1 = fmaxf(mn1, __shfl_xor_sync(FULL, mn1, 2));
        float c0 = __expf(m_r[0] - mn0);
        float c1 = __expf(m_r[1] - mn1);
        m_r[0] = mn0; m_r[1] = mn1;

        float pf_[8][4];
        float rs0 = 0.f, rs1 = 0.f;
        #pragma unroll
        for (int nt = 0; nt < 8; nt++) {
            pf_[nt][0] = __expf(s[nt][0] - mn0);
            pf_[nt][1] = __expf(s[nt][1] - mn0);
            pf_[nt][2] = __expf(s[nt][2] - mn1);
            pf_[nt][3] = __expf(s[nt][3] - mn1);
            rs0 += pf_[nt][0] + pf_[nt][1];
            rs1 += pf_[nt][2] + pf_[nt][3];
        }
        rs0 += __shfl_xor_sync(FULL, rs0, 1); rs0 += __shfl_xor_sync(FULL, rs0, 2);
        rs1 += __shfl_xor_sync(FULL, rs1, 1); rs1 += __shfl_xor_sync(FULL, rs1, 2);
        l_r[0] = l_r[0] * c0 + rs0;
        l_r[1] = l_r[1] * c1 + rs1;
        #pragma unroll
        for (int nt = 0; nt < 8; nt++) {
            o_acc[nt][0] *= c0; o_acc[nt][1] *= c0;
            o_acc[nt][2] *= c1; o_acc[nt][3] *= c1;
        }

        #pragma unroll
        for (int kk2 = 0; kk2 < 8; kk2++) {
            float v0 = pf_[kk2][0], v1 = pf_[kk2][1], v2 = pf_[kk2][2], v3 = pf_[kk2][3];
            float w0 = __shfl_sync(FULL, v0, srcA), w1 = __shfl_sync(FULL, v1, srcA);
            float w2 = __shfl_sync(FULL, v2, srcA), w3 = __shfl_sync(FULL, v3, srcA);
            float y0 = __shfl_sync(FULL, v0, srcB), y1 = __shfl_sync(FULL, v1, srcB);
            float y2 = __shfl_sync(FULL, v2, srcB), y3 = __shfl_sync(FULL, v3, srcB);
            bool odd = (tg & 1);
            uint32_t af[4];
            af[0] = f2tf32(odd ? w1 : w0);
            af[1] = f2tf32(odd ? w3 : w2);
            af[2] = f2tf32(odd ? y1 : y0);
            af[3] = f2tf32(odd ? y3 : y2);
            #pragma unroll
            for (int nt2 = 0; nt2 < 8; nt2++) {
                uint32_t bb[2];
                bb[0] = Vu[(kk2 * 8 + tg) * TW + nt2 * 8 + g];
                bb[1] = Vu[(kk2 * 8 + tg + 4) * TW + nt2 * 8 + g];
                mma_tf32(o_acc[nt2], af, bb);
            }
        }
        __syncthreads();
    }

    float inv0 = 1.0f / l_r[0], inv1 = 1.0f / l_r[1];
    float* Og = o + ((size_t)(b * NPp + q0 + w * 16 + g)) * Cc + h * HDd;
    #pragma unroll
    for (int nt2 = 0; nt2 < 8; nt2++) {
        int c = nt2 * 8 + 2 * tg;
        float2 r0v; r0v.x = rnd32(o_acc[nt2][0] * inv0); r0v.y = rnd32(o_acc[nt2][1] * inv0);
        float2 r1v; r1v.x = rnd32(o_acc[nt2][2] * inv1); r1v.y = rnd32(o_acc[nt2][3] * inv1);
        *reinterpret_cast<float2*>(Og + c) = r0v;
        *reinterpret_cast<float2*>(Og + (size_t)8 * Cc + c) = r1v;
    }
}

// ---------------- LayerNorm (tf32-rounded output) ----------------
__global__ void ln_kernel(const float* __restrict__ x, const float* __restrict__ g,
                          const float* __restrict__ b, float* __restrict__ out)
{
    size_t row = blockIdx.x;
    const float* xr = x + row * Cc;
    float* orow = out + row * Cc;
    int t = threadIdx.x;
    float4 v = reinterpret_cast<const float4*>(xr)[t];
    float s  = v.x + v.y + v.z + v.w;
    float ss = v.x*v.x + v.y*v.y + v.z*v.z + v.w*v.w;
    #pragma unroll
    for (int o = 16; o > 0; o >>= 1) {
        s  += __shfl_xor_sync(0xffffffffu, s,  o);
        ss += __shfl_xor_sync(0xffffffffu, ss, o);
    }
    __shared__ float r0[8], r1[8];
    if ((t & 31) == 0) { r0[t >> 5] = s; r1[t >> 5] = ss; }
    __syncthreads();
    s = 0.f; ss = 0.f;
    #pragma unroll
    for (int i = 0; i < 8; i++) { s += r0[i]; ss += r1[i]; }
    float mu  = s * (1.0f / Cc);
    float var = ss * (1.0f / Cc) - mu * mu;
    float inv = rsqrtf(var + 1e-5f);
    float4 gv = reinterpret_cast<const float4*>(g)[t];
    float4 bv = reinterpret_cast<const float4*>(b)[t];
    float4 r;
    r.x = rnd32((v.x - mu) * inv * gv.x + bv.x);
    r.y = rnd32((v.y - mu) * inv * gv.y + bv.y);
    r.z = rnd32((v.z - mu) * inv * gv.z + bv.z);
    r.w = rnd32((v.w - mu) * inv * gv.w + bv.w);
    reinterpret_cast<float4*>(orow)[t] = r;
}

// ---------------- mask scan: warp-parallel prefix scan ----------------
__global__ void p2t_kernel(const unsigned* __restrict__ mask)
{
    int b = blockIdx.x;
    int lane = threadIdx.x;
    const unsigned* mrow = mask + b * Nn;
    int base = lane * 32;
    unsigned bits = 0;
    int cnt = 0;
    #pragma unroll
    for (int i = 0; i < 32; i++) {
        unsigned mv = mrow[base + i] != 0u;
        bits |= mv << i;
        cnt += (int)mv;
    }
    int excl = cnt;
    #pragma unroll
    for (int o = 1; o < 32; o <<= 1) {
        int v = __shfl_up_sync(0xffffffffu, excl, o);
        if (lane >= o) excl += v;
    }
    excl -= cnt;
    int run = excl;
    #pragma unroll
    for (int i = 0; i < 32; i++) {
        bool mv = (bits >> i) & 1u;
        g_p2t[b * Nn + base + i] = mv ? run : -1;
        run += mv ? 1 : 0;
    }
}

// ---------------- KV fill (float4), pre-rounds to tf32 ----------------
__global__ void kvfill_kernel(const float4* __restrict__ ck, const float4* __restrict__ cv)
{
    size_t idx = (size_t)blockIdx.x * blockDim.x + threadIdx.x;
    int d4 = idx & 15;
    int n  = (idx >> 4) & (Nn - 1);
    int h  = (idx >> 14) & (Hh - 1);
    int b  = (int)(idx >> 18);
    int tok = g_p2t[b * Nn + n];
    float4 kv, vv;
    if (tok >= 0) {
        const float4* qkv4 = reinterpret_cast<const float4*>(g_qkv);
        size_t q = ((size_t)(b * NPp + tok)) * (C3 / 4) + (Cc / 4) + h * (HDd / 4) + d4;
        kv = qkv4[q];
        vv = qkv4[q + Cc / 4];
    } else {
        kv = ck[idx];
        vv = cv[idx];
    }
    kv.x = rnd32(kv.x); kv.y = rnd32(kv.y); kv.z = rnd32(kv.z); kv.w = rnd32(kv.w);
    vv.x = rnd32(vv.x); vv.y = rnd32(vv.y); vv.z = rnd32(vv.z); vv.w = rnd32(vv.w);
    reinterpret_cast<float4*>(g_kf)[idx] = kv;
    reinterpret_cast<float4*>(g_vf)[idx] = vv;
}

// ---------------- launch ----------------
extern "C" void kernel_launch(void* const* d_in, const int* in_sizes, int n_in,
                              void* d_out, int out_size)
{
    const float*    x      = (const float*)   d_in[0];
    const float*    cachek = (const float*)   d_in[1];
    const float*    cachev = (const float*)   d_in[2];
    const unsigned* mask   = (const unsigned*)d_in[3];
    const float*    qkv_w  = (const float*)   d_in[4];
    const float*    qkv_b  = (const float*)   d_in[5];
    const float*    proj_w = (const float*)   d_in[6];
    const float*    proj_b = (const float*)   d_in[7];
    const float*    n1_g   = (const float*)   d_in[8];
    const float*    n1_b   = (const float*)   d_in[9];
    const float*    n2_g   = (const float*)   d_in[10];
    const float*    n2_b   = (const float*)   d_in[11];
    const float*    fc1_w  = (const float*)   d_in[12];
    const float*    fc1_b  = (const float*)   d_in[13];
    const float*    fc2_w  = (const float*)   d_in[14];
    const float*    fc2_b  = (const float*)   d_in[15];
    float* out = (float*)d_out;

    float *h, *qkv, *kf, *vf, *o, *x1, *hid, *wq, *wp, *w1, *w2;
    cudaGetSymbolAddress((void**)&h,   g_h);
    cudaGetSymbolAddress((void**)&qkv, g_qkv);
    cudaGetSymbolAddress((void**)&kf,  g_kf);
    cudaGetSymbolAddress((void**)&vf,  g_vf);
    cudaGetSymbolAddress((void**)&o,   g_o);
    cudaGetSymbolAddress((void**)&x1,  g_x1);
    cudaGetSymbolAddress((void**)&hid, g_hid);
    cudaGetSymbolAddress((void**)&wq,  g_wq);
    cudaGetSymbolAddress((void**)&wp,  g_wp);
    cudaGetSymbolAddress((void**)&w1,  g_w1);
    cudaGetSymbolAddress((void**)&w2,  g_w2);

    const int GEMM_SMEM  = 3 * (128 * 20 + 16 * 136) * 4;   // 56832 B
    const int FLASH_SMEM = 2 * 2 * 64 * 68 * 4;             // 69632 B
    cudaFuncSetAttribute((const void*)mma_gemm<true, false, false, true>,
                         cudaFuncAttributeMaxDynamicSharedMemorySize, GEMM_SMEM);
    cudaFuncSetAttribute((const void*)mma_gemm<true, false, true, false>,
                         cudaFuncAttributeMaxDynamicSharedMemorySize, GEMM_SMEM);
    cudaFuncSetAttribute((const void*)mma_gemm<true, true, false, true>,
                         cudaFuncAttributeMaxDynamicSharedMemorySize, GEMM_SMEM);
    cudaFuncSetAttribute(flash_kernel,
                         cudaFuncAttributeMaxDynamicSharedMemorySize, FLASH_SMEM);

    // 0. pre-round all weights to tf32 (one launch)
    round_all_kernel<<<3145728 / 256, 256>>>(
        (const float4*)qkv_w, (const float4*)proj_w,
        (const float4*)fc1_w, (const float4*)fc2_w);

    // 1. LN1 (rounded out)
    ln_kernel<<<Mtok, 256>>>(x, n1_g, n1_b, h);

    // 2. QKV = h @ wq + qkv_b  (rounded out)
    mma_gemm<true, false, false, true><<<dim3(C3 / 128, Mtok / 128), 256, GEMM_SMEM>>>(
        h, wq, qkv, Cc, Cc, C3, C3, qkv_b, nullptr);

    // 3. mask scan (warp-parallel)
    p2t_kernel<<<Bb, 32>>>(mask);

    // 4. KV full fill (tf32-rounded)
    kvfill_kernel<<<((Bb * Hh * Nn * HDd) / 4) / 256, 256>>>(
        (const float4*)cachek, (const float4*)cachev);

    // 5-7. fused attention (o rounded out)
    flash_kernel<<<dim3(NPp / 128, Bb * Hh), 256, FLASH_SMEM>>>(qkv, kf, vf, o);

    // 8. x1 = x + o @ wp + proj_b
    mma_gemm<true, false, true, false><<<dim3(Cc / 128, Mtok / 128), 256, GEMM_SMEM>>>(
        o, wp, x1, Cc, Cc, Cc, Cc, proj_b, x);

    // 9. LN2 (rounded out)
    ln_kernel<<<Mtok, 256>>>(x1, n2_g, n2_b, h);

    // 10. hid = gelu(h @ w1 + fc1_b)  (rounded out)
    mma_gemm<true, true, false, true><<<dim3(HIDh / 128, Mtok / 128), 256, GEMM_SMEM>>>(
        h, w1, hid, Cc, Cc, HIDh, HIDh, fc1_b, nullptr);

    // 11. out = x1 + hid @ w2 + fc2_b
    mma_gemm<true, false, true, false><<<dim3(Cc / 128, Mtok / 128), 256, GEMM_SMEM>>>(
        hid, w2, out, HIDh, HIDh, Cc, Cc, fc2_b, x1);
}

// round 10
// speedup vs baseline: 1.1713x; 1.0873x over previous
#include <cuda_runtime.h>
#include <math.h>
#include <stdint.h>

// Problem constants
#define Bb   16
#define NPp  512
#define Nn   1024
#define Cc   1024
#define Hh   16
#define HDd  64
#define C3   3072
#define HIDh 4096
#define Mtok 8192   // B*NP

// ---------------- scratch (device globals) ----------------
__device__ float g_h   [(size_t)Mtok * Cc];
__device__ float g_qkv [(size_t)Mtok * C3];
__device__ float g_kf  [(size_t)Bb * Hh * Nn * HDd];
__device__ float g_vf  [(size_t)Bb * Hh * Nn * HDd];
__device__ float g_o   [(size_t)Mtok * Cc];
__device__ float g_x1  [(size_t)Mtok * Cc];
__device__ float g_hid [(size_t)Mtok * HIDh];
__device__ int   g_p2t [Bb * Nn];
// tf32-rounded weights
__device__ float g_wq  [(size_t)Cc * C3];
__device__ float g_wp  [(size_t)Cc * Cc];
__device__ float g_w1  [(size_t)Cc * HIDh];
__device__ float g_w2  [(size_t)HIDh * Cc];

// ---------------- helpers ----------------
__device__ __forceinline__ uint32_t f2tf32(float f) {
    uint32_t u;
    asm("cvt.rna.tf32.f32 %0, %1;" : "=r"(u) : "f"(f));
    return u;
}
__device__ __forceinline__ float rnd32(float f) { return __uint_as_float(f2tf32(f)); }

__device__ __forceinline__ void mma_tf32(float c[4], const uint32_t a[4], const uint32_t b[2]) {
    asm volatile(
        "mma.sync.aligned.m16n8k8.row.col.f32.tf32.tf32.f32 "
        "{%0,%1,%2,%3}, {%4,%5,%6,%7}, {%8,%9}, {%0,%1,%2,%3};"
        : "+f"(c[0]), "+f"(c[1]), "+f"(c[2]), "+f"(c[3])
        : "r"(a[0]), "r"(a[1]), "r"(a[2]), "r"(a[3]), "r"(b[0]), "r"(b[1]));
}
__device__ __forceinline__ void cp16(uint32_t saddr, const void* g) {
    asm volatile("cp.async.cg.shared.global [%0], [%1], 16;" :: "r"(saddr), "l"(g));
}
#define CP_COMMIT() asm volatile("cp.async.commit_group;")
#define CP_WAIT(n)  asm volatile("cp.async.wait_group %0;" :: "n"(n))

// ---------------- weight pre-round: all four weights in one launch ----------------
__global__ void round_all_kernel(const float4* __restrict__ wq_in, const float4* __restrict__ wp_in,
                                 const float4* __restrict__ w1_in, const float4* __restrict__ w2_in)
{
    const size_t NQ = (size_t)Cc * C3 / 4;
    const size_t NP_ = (size_t)Cc * Cc / 4;
    const size_t N1 = (size_t)Cc * HIDh / 4;
    const size_t N2 = (size_t)HIDh * Cc / 4;
    size_t i = (size_t)blockIdx.x * blockDim.x + threadIdx.x;
    const float4* src; float4* dst; size_t off;
    if (i < NQ)                    { src = wq_in; dst = (float4*)g_wq; off = i; }
    else if (i < NQ + NP_)         { src = wp_in; dst = (float4*)g_wp; off = i - NQ; }
    else if (i < NQ + NP_ + N1)    { src = w1_in; dst = (float4*)g_w1; off = i - NQ - NP_; }
    else if (i < NQ + NP_ + N1+N2) { src = w2_in; dst = (float4*)g_w2; off = i - NQ - NP_ - N1; }
    else return;
    float4 v = src[off];
    v.x = rnd32(v.x); v.y = rnd32(v.y); v.z = rnd32(v.z); v.w = rnd32(v.w);
    dst[off] = v;
}

// ---------------- tf32 mma.sync GEMM, cp.async 3-stage, BK=32 ----------------
// C[M,N] = act(A @ B + bias) + resid ;  A:[M,K] row-major, B:[K,N] row-major.
// BM=128, BN=128, BK=32; 256 thr = 8 warps, warp tile 64x32. 2 blocks/SM (16 warps).
template<bool HAS_BIAS, bool GELU_ACT, bool HAS_RES, bool ROUND_OUT>
__global__ void __launch_bounds__(256) mma_gemm(
    const float* __restrict__ A, const float* __restrict__ Bm, float* __restrict__ Cm,
    int K, int lda, int ldb, int ldc,
    const float* __restrict__ bias, const float* __restrict__ resid)
{
    const int AW = 36, BW = 136;                   // smem row strides (words)
    const int AWORDS = 128 * AW, BWORDS = 32 * BW; // 4608 + 4352
    const int STW = AWORDS + BWORDS;               // 8960 words per stage

    extern __shared__ float sm[];

    int t = threadIdx.x, lane = t & 31, warp = t >> 5;
    int g = lane >> 2, tg = lane & 3;
    int wm = (warp >> 2) * 64, wn = (warp & 3) * 32;
    int m0 = blockIdx.y * 128, n0 = blockIdx.x * 128;

    const float* Ab = A + (size_t)m0 * lda;
    const float* Bb_ = Bm + n0;

    float acc[4][4][4];
    #pragma unroll
    for (int i = 0; i < 4; i++)
        #pragma unroll
        for (int j = 0; j < 4; j++)
            #pragma unroll
            for (int l = 0; l < 4; l++) acc[i][j][l] = 0.f;

    auto issue = [&](int kt, int st) {
        float* As = sm + st * STW;
        float* Bs = As + AWORDS;
        const float* Ag = Ab + kt * 32;
        const float* Bg = Bb_ + (size_t)(kt * 32) * ldb;
        #pragma unroll
        for (int it = 0; it < 4; it++) {           // A: 128x32 = 1024 float4
            int c = t + it * 256;
            int r = c >> 3, c4 = (c & 7) * 4;
            cp16((uint32_t)__cvta_generic_to_shared(As + r * AW + c4),
                 Ag + (size_t)r * lda + c4);
        }
        #pragma unroll
        for (int it = 0; it < 4; it++) {           // B: 32x128 = 1024 float4
            int c = t + it * 256;
            int k = c >> 5, n4 = (c & 31) * 4;
            cp16((uint32_t)__cvta_generic_to_shared(Bs + k * BW + n4),
                 Bg + (size_t)k * ldb + n4);
        }
        CP_COMMIT();
    };

    auto compute = [&](int st) {
        const uint32_t* As = reinterpret_cast<const uint32_t*>(sm + st * STW);
        const uint32_t* Bs = As + AWORDS;
        #pragma unroll
        for (int ks = 0; ks < 4; ks++) {
            int k0 = ks * 8;
            uint32_t af[4][4], bf[4][2];
            #pragma unroll
            for (int mt = 0; mt < 4; mt++) {
                int r = wm + mt * 16 + g;
                af[mt][0] = As[r * AW + k0 + tg];
                af[mt][1] = As[(r + 8) * AW + k0 + tg];
                af[mt][2] = As[r * AW + k0 + tg + 4];
                af[mt][3] = As[(r + 8) * AW + k0 + tg + 4];
            }
            #pragma unroll
            for (int nt = 0; nt < 4; nt++) {
                int c = wn + nt * 8 + g;
                bf[nt][0] = Bs[(k0 + tg) * BW + c];
                bf[nt][1] = Bs[(k0 + tg + 4) * BW + c];
            }
            #pragma unroll
            for (int mt = 0; mt < 4; mt++)
                #pragma unroll
                for (int nt = 0; nt < 4; nt++)
                    mma_tf32(acc[mt][nt], af[mt], bf[nt]);
        }
    };

    const int KT = K / 32;
    issue(0, 0);
    issue(1, 1);

    for (int kt = 0; kt < KT; kt++) {
        if (kt + 1 < KT) { CP_WAIT(1); } else { CP_WAIT(0); }
        __syncthreads();
        compute(kt % 3);
        if (kt + 2 < KT) issue(kt + 2, (kt + 2) % 3);
    }

    // ---- epilogue ----
    #pragma unroll
    for (int mt = 0; mt < 4; mt++) {
        int r0 = m0 + wm + mt * 16 + g;
        #pragma unroll
        for (int nt = 0; nt < 4; nt++) {
            int c = n0 + wn + nt * 8 + 2 * tg;
            #pragma unroll
            for (int half = 0; half < 2; half++) {
                int r = r0 + half * 8;
                float v0 = acc[mt][nt][half * 2 + 0];
                float v1 = acc[mt][nt][half * 2 + 1];
                if (HAS_BIAS) { v0 += bias[c]; v1 += bias[c + 1]; }
                if (GELU_ACT) {
                    v0 = 0.5f * v0 * (1.0f + erff(v0 * 0.70710678118654752f));
                    v1 = 0.5f * v1 * (1.0f + erff(v1 * 0.70710678118654752f));
                }
                if (HAS_RES) {
                    float2 rv = *reinterpret_cast<const float2*>(
                        resid + (size_t)r * ldc + c);
                    v0 += rv.x; v1 += rv.y;
                }
                if (ROUND_OUT) { v0 = rnd32(v0); v1 = rnd32(v1); }
                float2 ov; ov.x = v0; ov.y = v1;
                *reinterpret_cast<float2*>(Cm + (size_t)r * ldc + c) = ov;
            }
        }
    }
}

// ---------------- fused flash attention (tf32 mma.sync) ----------------
__global__ void __launch_bounds__(256) flash_kernel(
    const float* __restrict__ qkv, const float* __restrict__ kf,
    const float* __restrict__ vf, float* __restrict__ o)
{
    extern __shared__ float fsm[];
    const int TW = 68;
    const int KWORDS = 64 * TW;

    int t = threadIdx.x, lane = t & 31, w = t >> 5;
    int g = lane >> 2, tg = lane & 3;
    int bh = blockIdx.y, b = bh >> 4, h = bh & 15;
    int q0 = blockIdx.x * 128;

    const float* Qg = qkv + ((size_t)(b * NPp + q0)) * C3 + h * HDd;
    #pragma unroll
    for (int it = 0; it < 8; it++) {
        int id = t + it * 256;
        int r = id >> 4, c4 = (id & 15) * 4;
        float4 v = *reinterpret_cast<const float4*>(Qg + (size_t)r * C3 + c4);
        float* d = fsm + r * TW + c4;
        d[0] = v.x; d[1] = v.y; d[2] = v.z; d[3] = v.w;
    }
    __syncthreads();

    uint32_t qf[8][4];
    {
        int r0 = w * 16 + g;
        #pragma unroll
        for (int kk = 0; kk < 8; kk++) {
            qf[kk][0] = f2tf32(fsm[r0 * TW + kk * 8 + tg] * 0.125f);
            qf[kk][1] = f2tf32(fsm[(r0 + 8) * TW + kk * 8 + tg] * 0.125f);
            qf[kk][2] = f2tf32(fsm[r0 * TW + kk * 8 + tg + 4] * 0.125f);
            qf[kk][3] = f2tf32(fsm[(r0 + 8) * TW + kk * 8 + tg + 4] * 0.125f);
        }
    }
    __syncthreads();

    const float* Kg = kf + (size_t)bh * Nn * HDd;
    const float* Vg = vf + (size_t)bh * Nn * HDd;

    auto issue_tile = [&](int j, int buf) {
        float* Ks = fsm + buf * (2 * KWORDS);
        float* Vs = Ks + KWORDS;
        const float* kg = Kg + (size_t)j * 64 * HDd;
        const float* vg = Vg + (size_t)j * 64 * HDd;
        #pragma unroll
        for (int it = 0; it < 4; it++) {
            int id = t + it * 256;
            int r = id >> 4, c4 = (id & 15) * 4;
            cp16((uint32_t)__cvta_generic_to_shared(Ks + r * TW + c4), kg + r * HDd + c4);
            cp16((uint32_t)__cvta_generic_to_shared(Vs + r * TW + c4), vg + r * HDd + c4);
        }
    };

    float m_r[2] = {-1e30f, -1e30f};
    float l_r[2] = {0.f, 0.f};
    float o_acc[8][4];
    #pragma unroll
    for (int i = 0; i < 8; i++)
        #pragma unroll
        for (int j = 0; j < 4; j++) o_acc[i][j] = 0.f;

    const unsigned FULL = 0xffffffffu;
    const int srcA = (lane & ~3) | (tg >> 1);
    const int srcB = srcA + 2;

    issue_tile(0, 0);
    CP_COMMIT();

    for (int j = 0; j < Nn / 64; j++) {
        int buf = j & 1;
        if (j + 1 < Nn / 64) { issue_tile(j + 1, buf ^ 1); CP_COMMIT(); CP_WAIT(1); }
        else                 { CP_WAIT(0); }
        __syncthreads();

        const uint32_t* Ku = reinterpret_cast<const uint32_t*>(fsm + buf * (2 * KWORDS));
        const uint32_t* Vu = Ku + KWORDS;

        float s[8][4];
        #pragma unroll
        for (int nt = 0; nt < 8; nt++)
            #pragma unroll
            for (int i = 0; i < 4; i++) s[nt][i] = 0.f;
        #pragma unroll
        for (int kk = 0; kk < 8; kk++) {
            #pragma unroll
            for (int nt = 0; nt < 8; nt++) {
                uint32_t bb[2];
                bb[0] = Ku[(nt * 8 + g) * TW + kk * 8 + tg];
                bb[1] = Ku[(nt * 8 + g) * TW + kk * 8 + tg + 4];
                mma_tf32(s[nt], qf[kk], bb);
            }
        }

        float mn0 = m_r[0], mn1 = m_r[1];
        #pragma unroll
        for (int nt = 0; nt < 8; nt++) {
            mn0 = fmaxf(mn0, fmaxf(s[nt][0], s[nt][1]));
            mn1 = fmaxf(mn1, fmaxf(s[nt][2], s[nt][3]));
        }
        mn0 = fmaxf(mn0, __shfl_xor_sync(FULL, mn0, 1));
        mn0 = fmaxf(mn0, __shfl_xor_sync(FULL, mn0, 2));
        mn1 = fmaxf(mn1, __shfl_xor_sync(FULL, mn1, 1));
        mn1 = fmaxf(mn1, __shfl_xor_sync(FULL, mn1, 2));
        float c0 = __expf(m_r[0] - mn0);
        float c1 = __expf(m_r[1] - mn1);
        m_r[0] = mn0; m_r[1] = mn1;

        float pf_[8][4];
        float rs0 = 0.f, rs1 = 0.f;
        #pragma unroll
        for (int nt = 0; nt < 8; nt++) {
            pf_[nt][0] = __expf(s[nt][0] - mn0);
            pf_[nt][1] = __expf(s[nt][1] - mn0);
            pf_[nt][2] = __expf(s[nt][2] - mn1);
            pf_[nt][3] = __expf(s[nt][3] - mn1);
            rs0 += pf_[nt][0] + pf_[nt][1];
            rs1 += pf_[nt][2] + pf_[nt][3];
        }
        rs0 += __shfl_xor_sync(FULL, rs0, 1); rs0 += __shfl_xor_sync(FULL, rs0, 2);
        rs1 += __shfl_xor_sync(FULL, rs1, 1); rs1 += __shfl_xor_sync(FULL, rs1, 2);
        l_r[0] = l_r[0] * c0 + rs0;
        l_r[1] = l_r[1] * c1 + rs1;
        #pragma unroll
        for (int nt = 0; nt < 8; nt++) {
            o_acc[nt][0] *= c0; o_acc[nt][1] *= c0;
            o_acc[nt][2] *= c1; o_acc[nt][3] *= c1;
        }

        #pragma unroll
        for (int kk2 = 0; kk2 < 8; kk2++) {
            float v0 = pf_[kk2][0], v1 = pf_[kk2][1], v2 = pf_[kk2][2], v3 = pf_[kk2][3];
            float w0 = __shfl_sync(FULL, v0, srcA), w1 = __shfl_sync(FULL, v1, srcA);
            float w2 = __shfl_sync(FULL, v2, srcA), w3 = __shfl_sync(FULL, v3, srcA);
            float y0 = __shfl_sync(FULL, v0, srcB), y1 = __shfl_sync(FULL, v1, srcB);
            float y2 = __shfl_sync(FULL, v2, srcB), y3 = __shfl_sync(FULL, v3, srcB);
            bool odd = (tg & 1);
            uint32_t af[4];
            af[0] = f2tf32(odd ? w1 : w0);
            af[1] = f2tf32(odd ? w3 : w2);
            af[2] = f2tf32(odd ? y1 : y0);
            af[3] = f2tf32(odd ? y3 : y2);
            #pragma unroll
            for (int nt2 = 0; nt2 < 8; nt2++) {
                uint32_t bb[2];
                bb[0] = Vu[(kk2 * 8 + tg) * TW + nt2 * 8 + g];
                bb[1] = Vu[(kk2 * 8 + tg + 4) * TW + nt2 * 8 + g];
                mma_tf32(o_acc[nt2], af, bb);
            }
        }
        __syncthreads();
    }

    float inv0 = 1.0f / l_r[0], inv1 = 1.0f / l_r[1];
    float* Og = o + ((size_t)(b * NPp + q0 + w * 16 + g)) * Cc + h * HDd;
    #pragma unroll
    for (int nt2 = 0; nt2 < 8; nt2++) {
        int c = nt2 * 8 + 2 * tg;
        float2 r0v; r0v.x = rnd32(o_acc[nt2][0] * inv0); r0v.y = rnd32(o_acc[nt2][1] * inv0);
        float2 r1v; r1v.x = rnd32(o_acc[nt2][2] * inv1); r1v.y = rnd32(o_acc[nt2][3] * inv1);
        *reinterpret_cast<float2*>(Og + c) = r0v;
        *reinterpret_cast<float2*>(Og + (size_t)8 * Cc + c) = r1v;
    }
}

// ---------------- LayerNorm (tf32-rounded output) ----------------
__global__ void ln_kernel(const float* __restrict__ x, const float* __restrict__ g,
                          const float* __restrict__ b, float* __restrict__ out)
{
    size_t row = blockIdx.x;
    const float* xr = x + row * Cc;
    float* orow = out + row * Cc;
    int t = threadIdx.x;
    float4 v = reinterpret_cast<const float4*>(xr)[t];
    float s  = v.x + v.y + v.z + v.w;
    float ss = v.x*v.x + v.y*v.y + v.z*v.z + v.w*v.w;
    #pragma unroll
    for (int o = 16; o > 0; o >>= 1) {
        s  += __shfl_xor_sync(0xffffffffu, s,  o);
        ss += __shfl_xor_sync(0xffffffffu, ss, o);
    }
    __shared__ float r0[8], r1[8];
    if ((t & 31) == 0) { r0[t >> 5] = s; r1[t >> 5] = ss; }
    __syncthreads();
    s = 0.f; ss = 0.f;
    #pragma unroll
    for (int i = 0; i < 8; i++) { s += r0[i]; ss += r1[i]; }
    float mu  = s * (1.0f / Cc);
    float var = ss * (1.0f / Cc) - mu * mu;
    float inv = rsqrtf(var + 1e-5f);
    float4 gv = reinterpret_cast<const float4*>(g)[t];
    float4 bv = reinterpret_cast<const float4*>(b)[t];
    float4 r;
    r.x = rnd32((v.x - mu) * inv * gv.x + bv.x);
    r.y = rnd32((v.y - mu) * inv * gv.y + bv.y);
    r.z = rnd32((v.z - mu) * inv * gv.z + bv.z);
    r.w = rnd32((v.w - mu) * inv * gv.w + bv.w);
    reinterpret_cast<float4*>(orow)[t] = r;
}

// ---------------- mask scan: warp-parallel prefix scan ----------------
__global__ void p2t_kernel(const unsigned* __restrict__ mask)
{
    int b = blockIdx.x;
    int lane = threadIdx.x;
    const unsigned* mrow = mask + b * Nn;
    int base = lane * 32;
    unsigned bits = 0;
    int cnt = 0;
    #pragma unroll
    for (int i = 0; i < 32; i++) {
        unsigned mv = mrow[base + i] != 0u;
        bits |= mv << i;
        cnt += (int)mv;
    }
    int excl = cnt;
    #pragma unroll
    for (int o = 1; o < 32; o <<= 1) {
        int v = __shfl_up_sync(0xffffffffu, excl, o);
        if (lane >= o) excl += v;
    }
    excl -= cnt;
    int run = excl;
    #pragma unroll
    for (int i = 0; i < 32; i++) {
        bool mv = (bits >> i) & 1u;
        g_p2t[b * Nn + base + i] = mv ? run : -1;
        run += mv ? 1 : 0;
    }
}

// ---------------- KV fill (float4), pre-rounds to tf32 ----------------
__global__ void kvfill_kernel(const float4* __restrict__ ck, const float4* __restrict__ cv)
{
    size_t idx = (size_t)blockIdx.x * blockDim.x + threadIdx.x;
    int d4 = idx & 15;
    int n  = (idx >> 4) & (Nn - 1);
    int h  = (idx >> 14) & (Hh - 1);
    int b  = (int)(idx >> 18);
    int tok = g_p2t[b * Nn + n];
    float4 kv, vv;
    if (tok >= 0) {
        const float4* qkv4 = reinterpret_cast<const float4*>(g_qkv);
        size_t q = ((size_t)(b * NPp + tok)) * (C3 / 4) + (Cc / 4) + h * (HDd / 4) + d4;
        kv = qkv4[q];
        vv = qkv4[q + Cc / 4];
    } else {
        kv = ck[idx];
        vv = cv[idx];
    }
    kv.x = rnd32(kv.x); kv.y = rnd32(kv.y); kv.z = rnd32(kv.z); kv.w = rnd32(kv.w);
    vv.x = rnd32(vv.x); vv.y = rnd32(vv.y); vv.z = rnd32(vv.z); vv.w = rnd32(vv.w);
    reinterpret_cast<float4*>(g_kf)[idx] = kv;
    reinterpret_cast<float4*>(g_vf)[idx] = vv;
}

// ---------------- launch ----------------
extern "C" void kernel_launch(void* const* d_in, const int* in_sizes, int n_in,
                              void* d_out, int out_size)
{
    const float*    x      = (const float*)   d_in[0];
    const float*    cachek = (const float*)   d_in[1];
    const float*    cachev = (const float*)   d_in[2];
    const unsigned* mask   = (const unsigned*)d_in[3];
    const float*    qkv_w  = (const float*)   d_in[4];
    const float*    qkv_b  = (const float*)   d_in[5];
    const float*    proj_w = (const float*)   d_in[6];
    const float*    proj_b = (const float*)   d_in[7];
    const float*    n1_g   = (const float*)   d_in[8];
    const float*    n1_b   = (const float*)   d_in[9];
    const float*    n2_g   = (const float*)   d_in[10];
    const float*    n2_b   = (const float*)   d_in[11];
    const float*    fc1_w  = (const float*)   d_in[12];
    const float*    fc1_b  = (const float*)   d_in[13];
    const float*    fc2_w  = (const float*)   d_in[14];
    const float*    fc2_b  = (const float*)   d_in[15];
    float* out = (float*)d_out;

    float *h, *qkv, *kf, *vf, *o, *x1, *hid, *wq, *wp, *w1, *w2;
    cudaGetSymbolAddress((void**)&h,   g_h);
    cudaGetSymbolAddress((void**)&qkv, g_qkv);
    cudaGetSymbolAddress((void**)&kf,  g_kf);
    cudaGetSymbolAddress((void**)&vf,  g_vf);
    cudaGetSymbolAddress((void**)&o,   g_o);
    cudaGetSymbolAddress((void**)&x1,  g_x1);
    cudaGetSymbolAddress((void**)&hid, g_hid);
    cudaGetSymbolAddress((void**)&wq,  g_wq);
    cudaGetSymbolAddress((void**)&wp,  g_wp);
    cudaGetSymbolAddress((void**)&w1,  g_w1);
    cudaGetSymbolAddress((void**)&w2,  g_w2);

    const int GEMM_SMEM  = 3 * (128 * 36 + 32 * 136) * 4;   // 107520 B
    const int FLASH_SMEM = 2 * 2 * 64 * 68 * 4;             // 69632 B
    cudaFuncSetAttribute((const void*)mma_gemm<true, false, false, true>,
                         cudaFuncAttributeMaxDynamicSharedMemorySize, GEMM_SMEM);
    cudaFuncSetAttribute((const void*)mma_gemm<true, false, true, false>,
                         cudaFuncAttributeMaxDynamicSharedMemorySize, GEMM_SMEM);
    cudaFuncSetAttribute((const void*)mma_gemm<true, true, false, true>,
                         cudaFuncAttributeMaxDynamicSharedMemorySize, GEMM_SMEM);
    cudaFuncSetAttribute(flash_kernel,
                         cudaFuncAttributeMaxDynamicSharedMemorySize, FLASH_SMEM);

    // 0. pre-round all weights to tf32 (one launch)
    round_all_kernel<<<3145728 / 256, 256>>>(
        (const float4*)qkv_w, (const float4*)proj_w,
        (const float4*)fc1_w, (const float4*)fc2_w);

    // 1. LN1 (rounded out)
    ln_kernel<<<Mtok, 256>>>(x, n1_g, n1_b, h);

    // 2. QKV = h @ wq + qkv_b  (rounded out)
    mma_gemm<true, false, false, true><<<dim3(C3 / 128, Mtok / 128), 256, GEMM_SMEM>>>(
        h, wq, qkv, Cc, Cc, C3, C3, qkv_b, nullptr);

    // 3. mask scan (warp-parallel)
    p2t_kernel<<<Bb, 32>>>(mask);

    // 4. KV full fill (tf32-rounded)
    kvfill_kernel<<<((Bb * Hh * Nn * HDd) / 4) / 256, 256>>>(
        (const float4*)cachek, (const float4*)cachev);

    // 5-7. fused attention (o rounded out)
    flash_kernel<<<dim3(NPp / 128, Bb * Hh), 256, FLASH_SMEM>>>(qkv, kf, vf, o);

    // 8. x1 = x + o @ wp + proj_b
    mma_gemm<true, false, true, false><<<dim3(Cc / 128, Mtok / 128), 256, GEMM_SMEM>>>(
        o, wp, x1, Cc, Cc, Cc, Cc, proj_b, x);

    // 9. LN2 (rounded out)
    ln_kernel<<<Mtok, 256>>>(x1, n2_g, n2_b, h);

    // 10. hid = gelu(h @ w1 + fc1_b)  (rounded out)
    mma_gemm<true, true, false, true><<<dim3(HIDh / 128, Mtok / 128), 256, GEMM_SMEM>>>(
        h, w1, hid, Cc, Cc, HIDh, HIDh, fc1_b, nullptr);

    // 11. out = x1 + hid @ w2 + fc2_b
    mma_gemm<true, false, true, false><<<dim3(Cc / 128, Mtok / 128), 256, GEMM_SMEM>>>(
        hid, w2, out, HIDh, HIDh, Cc, Cc, fc2_b, x1);
}